// round 1
// baseline (speedup 1.0000x reference)
#include <cuda_runtime.h>
#include <math.h>
#include <stdint.h>

#define NN 50000
#define FF 128
#define HH 256
#define CC 512
#define EE 800000

// ---------------- scratch (device globals; no allocation allowed) -------------
__device__ int      g_cnt[NN];
__device__ int      g_rowstart[NN];
__device__ int      g_fill[NN];
__device__ int      g_incl[NN];
__device__ int      g_bsum[64];
__device__ int      g_csr[EE];
__device__ float    g_inv[NN];
__device__ float    g_hs[NN];
__device__ float    g_invs[NN];
__device__ float    g_score[NN];
__device__ int      g_cluster[NN];
__device__ unsigned g_cmaxkey[CC];
__device__ int      g_idx[CC];
__device__ int      g_nonempty[CC];
__device__ float    g_P[(size_t)NN * HH];   // propagation output (<=256 feats)
__device__ float    g_h[(size_t)NN * HH];   // hidden activations
__device__ float    g_h3[(size_t)NN * CC];  // layer-3 pre-softmax

// monotonic float<->uint key for atomicMax on floats
__device__ __forceinline__ unsigned fkey(float f) {
    unsigned u = __float_as_uint(f);
    return (u & 0x80000000u) ? ~u : (u | 0x80000000u);
}
__device__ __forceinline__ float fdec(unsigned k) {
    return (k & 0x80000000u) ? __uint_as_float(k ^ 0x80000000u)
                             : __uint_as_float(~k);
}

// ---------------- setup kernels ----------------------------------------------
__global__ void k_init() {
    int i = blockIdx.x * blockDim.x + threadIdx.x;
    if (i < NN) g_cnt[i] = 0;
    if (i < CC) { g_cmaxkey[i] = 0u; g_idx[i] = 0x7FFFFFFF; g_nonempty[i] = 0; }
}

__global__ void k_count(const int* __restrict__ dst) {
    int e = blockIdx.x * blockDim.x + threadIdx.x;
    if (e < EE) atomicAdd(&g_cnt[dst[e]], 1);
}

__global__ void k_scan1() {  // per-1024 block inclusive scan of g_cnt -> g_incl, block sums
    __shared__ int s[1024];
    int g = blockIdx.x * 1024 + threadIdx.x;
    int v = (g < NN) ? g_cnt[g] : 0;
    s[threadIdx.x] = v;
    __syncthreads();
    for (int off = 1; off < 1024; off <<= 1) {
        int t = (threadIdx.x >= off) ? s[threadIdx.x - off] : 0;
        __syncthreads();
        s[threadIdx.x] += t;
        __syncthreads();
    }
    if (g < NN) g_incl[g] = s[threadIdx.x];
    if (threadIdx.x == 1023) g_bsum[blockIdx.x] = s[1023];
}

__global__ void k_scan2(int nb) {  // serial exclusive scan of block sums (tiny)
    if (threadIdx.x == 0 && blockIdx.x == 0) {
        int a = 0;
        for (int i = 0; i < nb; i++) { int t = g_bsum[i]; g_bsum[i] = a; a += t; }
    }
}

__global__ void k_scan3() {
    int g = blockIdx.x * blockDim.x + threadIdx.x;
    if (g < NN) {
        int rs = g_incl[g] + g_bsum[g >> 10] - g_cnt[g];
        g_rowstart[g] = rs;
        g_fill[g] = rs;
        g_inv[g] = rsqrtf((float)g_cnt[g] + 1.0f);
    }
}

__global__ void k_scatter(const int* __restrict__ src, const int* __restrict__ dst) {
    int e = blockIdx.x * blockDim.x + threadIdx.x;
    if (e < EE) {
        int p = atomicAdd(&g_fill[dst[e]], 1);
        g_csr[p] = src[e];
    }
}

// ---------------- GCN propagation: Y[i] = inv[i]*(inv[i]*X[i] + sum inv[s]*X[s]) ---
template <int F>
__global__ void k_prop(const float* __restrict__ X, float* __restrict__ Y) {
    int i = blockIdx.x;
    int f = threadIdx.x;  // blockDim == F
    float invi = g_inv[i];
    float acc = invi * X[(size_t)i * F + f];
    int beg = g_rowstart[i];
    int end = beg + g_cnt[i];
    int j = beg;
    for (; j + 1 < end; j += 2) {
        int s0 = g_csr[j], s1 = g_csr[j + 1];
        float a0 = g_inv[s0] * X[(size_t)s0 * F + f];
        float a1 = g_inv[s1] * X[(size_t)s1 * F + f];
        acc += a0 + a1;
    }
    if (j < end) {
        int s0 = g_csr[j];
        acc += g_inv[s0] * X[(size_t)s0 * F + f];
    }
    Y[(size_t)i * F + f] = invi * acc;
}

// ---------------- SGEMM: C[M,N] = A[M,K] @ B[K,N] + bias (optional relu) ------
#define BM 128
#define BN 64
#define BK 16
__global__ __launch_bounds__(256) void k_gemm(
    const float* __restrict__ A, const float* __restrict__ B,
    const float* __restrict__ bias, float* __restrict__ C,
    int M, int N, int K, int doRelu) {
    __shared__ float As[BK][BM + 4];
    __shared__ float Bs[BK][BN];
    int tid = threadIdx.x;
    int tx = tid & 15, ty = tid >> 4;
    int m0 = blockIdx.y * BM;
    int n0 = blockIdx.x * BN;
    int la_col = tid & 15;      // k in tile
    int la_row = tid >> 4;      // 0..15
    int lb_row = tid >> 4;      // 0..15
    int lb_col = (tid & 15) * 4;
    float acc[8][4];
#pragma unroll
    for (int i = 0; i < 8; i++)
#pragma unroll
        for (int jj = 0; jj < 4; jj++) acc[i][jj] = 0.0f;

    for (int k0 = 0; k0 < K; k0 += BK) {
#pragma unroll
        for (int r = 0; r < 8; r++) {
            int m = m0 + la_row + r * 16;
            float v = (m < M) ? A[(size_t)m * K + k0 + la_col] : 0.0f;
            As[la_col][la_row + r * 16] = v;
        }
        float4 bv = *(const float4*)&B[(size_t)(k0 + lb_row) * N + n0 + lb_col];
        *(float4*)&Bs[lb_row][lb_col] = bv;
        __syncthreads();
#pragma unroll
        for (int kk = 0; kk < BK; kk++) {
            float4 a0 = *(const float4*)&As[kk][ty * 8];
            float4 a1 = *(const float4*)&As[kk][ty * 8 + 4];
            float4 b0 = *(const float4*)&Bs[kk][tx * 4];
            float a[8] = {a0.x, a0.y, a0.z, a0.w, a1.x, a1.y, a1.z, a1.w};
            float b[4] = {b0.x, b0.y, b0.z, b0.w};
#pragma unroll
            for (int i = 0; i < 8; i++)
#pragma unroll
                for (int jj = 0; jj < 4; jj++) acc[i][jj] += a[i] * b[jj];
        }
        __syncthreads();
    }
#pragma unroll
    for (int i = 0; i < 8; i++) {
        int m = m0 + ty * 8 + i;
        if (m >= M) continue;
#pragma unroll
        for (int jj = 0; jj < 4; jj++) {
            int n = n0 + tx * 4 + jj;
            float v = acc[i][jj] + bias[n];
            if (doRelu) v = fmaxf(v, 0.0f);
            C[(size_t)m * N + n] = v;
        }
    }
}

// ---------------- softmax(relu(h3)) row-wise + argmax -------------------------
__global__ __launch_bounds__(512) void k_softmax(const float* __restrict__ H,
                                                 float* __restrict__ S) {
    __shared__ float sv[512];
    __shared__ int si[512];
    int i = blockIdx.x, c = threadIdx.x;
    float z = fmaxf(H[(size_t)i * CC + c], 0.0f);
    sv[c] = z; si[c] = c;
    __syncthreads();
    for (int off = 256; off > 0; off >>= 1) {
        if (c < off) {
            float v2 = sv[c + off]; int i2 = si[c + off];
            if (v2 > sv[c] || (v2 == sv[c] && i2 < si[c])) { sv[c] = v2; si[c] = i2; }
        }
        __syncthreads();
    }
    float m = sv[0]; int am = si[0];
    __syncthreads();
    float e = expf(z - m);
    sv[c] = e;
    __syncthreads();
    for (int off = 256; off > 0; off >>= 1) {
        if (c < off) sv[c] += sv[c + off];
        __syncthreads();
    }
    float invsum = 1.0f / sv[0];
    S[(size_t)i * CC + c] = e * invsum;
    if (c == 0) g_cluster[i] = am;
}

// ---------------- score layer ------------------------------------------------
__global__ void k_hs(const float* __restrict__ x, const float* __restrict__ Ws) {
    int t = blockIdx.x * blockDim.x + threadIdx.x;
    int w = t >> 5, lane = t & 31;
    if (w >= NN) return;
    float a = 0.0f;
#pragma unroll
    for (int r = 0; r < 4; r++) {
        int f = lane + 32 * r;
        a += x[(size_t)w * FF + f] * Ws[f];
    }
#pragma unroll
    for (int off = 16; off > 0; off >>= 1) a += __shfl_down_sync(0xFFFFFFFFu, a, off);
    if (lane == 0) g_hs[w] = a;
}

__global__ void k_intra() {  // per node: count intra in-edges; mark cluster nonempty
    int t = blockIdx.x * blockDim.x + threadIdx.x;
    int i = t >> 5, lane = t & 31;
    if (i >= NN) return;
    int myc = g_cluster[i];
    int beg = g_rowstart[i], end = beg + g_cnt[i];
    int cint = 0;
    for (int j = beg + lane; j < end; j += 32)
        cint += (g_cluster[g_csr[j]] == myc) ? 1 : 0;
#pragma unroll
    for (int off = 16; off > 0; off >>= 1) cint += __shfl_down_sync(0xFFFFFFFFu, cint, off);
    if (lane == 0) {
        g_invs[i] = rsqrtf((float)cint + 1.0f);
        if (cint > 0) atomicOr(&g_nonempty[myc], 1);
    }
}

__global__ void k_score(const float* __restrict__ bs) {
    int t = blockIdx.x * blockDim.x + threadIdx.x;
    int i = t >> 5, lane = t & 31;
    if (i >= NN) return;
    int myc = g_cluster[i];
    int beg = g_rowstart[i], end = beg + g_cnt[i];
    float acc = 0.0f;
    for (int j = beg + lane; j < end; j += 32) {
        int s = g_csr[j];
        if (g_cluster[s] == myc) acc += g_invs[s] * g_hs[s];
    }
#pragma unroll
    for (int off = 16; off > 0; off >>= 1) acc += __shfl_down_sync(0xFFFFFFFFu, acc, off);
    if (lane == 0) {
        float invi = g_invs[i];
        float agg = invi * (acc + invi * g_hs[i]);
        g_score[i] = tanhf(agg + bs[0]);
    }
}

__global__ void k_segmax() {
    int i = blockIdx.x * blockDim.x + threadIdx.x;
    if (i < NN) atomicMax(&g_cmaxkey[g_cluster[i]], fkey(g_score[i]));
}

__global__ void k_argidx() {
    int i = blockIdx.x * blockDim.x + threadIdx.x;
    if (i < NN && fkey(g_score[i]) >= g_cmaxkey[g_cluster[i]])
        atomicMin(&g_idx[g_cluster[i]], i);
}

// ---------------- outputs ----------------------------------------------------
__global__ void k_newx(const float* __restrict__ x, float* __restrict__ out) {
    int c = blockIdx.x, f = threadIdx.x;  // CC blocks x FF threads
    float v = 0.0f;
    if (g_nonempty[c]) {
        float alpha = fdec(g_cmaxkey[c]);
        int id = g_idx[c];
        v = x[(size_t)id * FF + f] * alpha;
    }
    out[(size_t)c * FF + f] = v;
}

__global__ void k_zero(float* __restrict__ p, int n) {
    int i = blockIdx.x * blockDim.x + threadIdx.x;
    if (i < n) p[i] = 0.0f;
}

__global__ void k_adj(const int* __restrict__ src, const int* __restrict__ dst,
                      float* __restrict__ adj) {
    int e = blockIdx.x * blockDim.x + threadIdx.x;
    if (e >= EE) return;
    int ci = g_cluster[src[e]], cj = g_cluster[dst[e]];
    if (ci != cj && g_nonempty[ci] && g_nonempty[cj]) adj[ci * CC + cj] = 1.0f;
}

// ---------------- host -------------------------------------------------------
extern "C" void kernel_launch(void* const* d_in, const int* in_sizes, int n_in,
                              void* d_out, int out_size) {
    const float* x  = (const float*)d_in[0];
    const int*   ei = (const int*)d_in[1];
    const int*   src = ei;
    const int*   dst = ei + EE;
    const float* W1 = (const float*)d_in[3];
    const float* b1 = (const float*)d_in[4];
    const float* W2 = (const float*)d_in[5];
    const float* b2 = (const float*)d_in[6];
    const float* W3 = (const float*)d_in[7];
    const float* b3 = (const float*)d_in[8];
    const float* Ws = (const float*)d_in[9];
    const float* bs = (const float*)d_in[10];

    float* out      = (float*)d_out;
    float* out_newx = out;
    float* out_adj  = out + (size_t)CC * FF;
    float* out_S    = out + (size_t)CC * FF + (size_t)CC * CC + CC;

    float *pP, *ph, *ph3;
    cudaGetSymbolAddress((void**)&pP,  g_P);
    cudaGetSymbolAddress((void**)&ph,  g_h);
    cudaGetSymbolAddress((void**)&ph3, g_h3);

    const int TB = 256;
    int gN = (NN + TB - 1) / TB;
    int gE = (EE + TB - 1) / TB;
    int gW = (NN * 32 + TB - 1) / TB;  // warp-per-node kernels
    int nbScan = (NN + 1023) / 1024;

    // graph build (CSR) + degree normalization
    k_init<<<gN, TB>>>();
    k_count<<<gE, TB>>>(dst);
    k_scan1<<<nbScan, 1024>>>();
    k_scan2<<<1, 32>>>(nbScan);
    k_scan3<<<gN, TB>>>();
    k_scatter<<<gE, TB>>>(src, dst);

    // 3-layer GCN (propagate in input space, then linear+bias+relu)
    dim3 gemmGrid1(HH / BN, (NN + BM - 1) / BM);
    dim3 gemmGrid3(CC / BN, (NN + BM - 1) / BM);
    k_prop<FF><<<NN, FF>>>(x, pP);
    k_gemm<<<gemmGrid1, 256>>>(pP, W1, b1, ph, NN, HH, FF, 1);
    k_prop<HH><<<NN, HH>>>(ph, pP);
    k_gemm<<<gemmGrid1, 256>>>(pP, W2, b2, ph, NN, HH, HH, 1);
    k_prop<HH><<<NN, HH>>>(ph, pP);
    k_gemm<<<gemmGrid3, 256>>>(pP, W3, b3, ph3, NN, CC, HH, 0);

    // softmax(relu) -> S output + hard clusters
    k_softmax<<<NN, 512>>>(ph3, out_S);

    // score layer on intra-cluster subgraph
    k_hs<<<gW, TB>>>(x, Ws);
    k_intra<<<gW, TB>>>();
    k_score<<<gW, TB>>>(bs);
    k_segmax<<<gN, TB>>>();
    k_argidx<<<gN, TB>>>();

    // pooled outputs: new_x, new_adj, new_batch (batch is all zeros)
    k_newx<<<CC, FF>>>(x, out_newx);
    int zn = CC * CC + CC;  // adjacency + new_batch region
    k_zero<<<(zn + TB - 1) / TB, TB>>>(out_adj, zn);
    k_adj<<<gE, TB>>>(src, dst, out_adj);
}

// round 3
// speedup vs baseline: 1.5973x; 1.5973x over previous
#include <cuda_runtime.h>
#include <math.h>
#include <stdint.h>

#define NN 50000
#define FF 128
#define HH 256
#define CC 512
#define EE 800000

// ---------------- scratch (device globals; no allocation allowed) -------------
__device__ int      g_cnt[NN];
__device__ int      g_rowstart[NN];
__device__ int      g_fill[NN];
__device__ int      g_incl[NN];
__device__ int      g_bsum[64];
__device__ int      g_csr[EE];
__device__ float    g_inv[NN];
__device__ float    g_hs[NN];
__device__ float    g_invs[NN];
__device__ float    g_score[NN];
__device__ int      g_cluster[NN];
__device__ unsigned g_cmaxkey[CC];
__device__ int      g_idx[CC];
__device__ int      g_nonempty[CC];
__device__ float    g_P[(size_t)NN * HH];   // propagation output (<=256 feats)
__device__ float    g_h[(size_t)NN * HH];   // hidden activations
__device__ float    g_h3[(size_t)NN * CC];  // layer-3 pre-softmax

// monotonic float<->uint key for atomicMax on floats
__device__ __forceinline__ unsigned fkey(float f) {
    unsigned u = __float_as_uint(f);
    return (u & 0x80000000u) ? ~u : (u | 0x80000000u);
}
__device__ __forceinline__ float fdec(unsigned k) {
    return (k & 0x80000000u) ? __uint_as_float(k ^ 0x80000000u)
                             : __uint_as_float(~k);
}

// ---------------- setup kernels ----------------------------------------------
__global__ void k_init() {
    int i = blockIdx.x * blockDim.x + threadIdx.x;
    if (i < NN) g_cnt[i] = 0;
    if (i < CC) { g_cmaxkey[i] = 0u; g_idx[i] = 0x7FFFFFFF; g_nonempty[i] = 0; }
}

__global__ void k_count(const int* __restrict__ dst) {
    int e = blockIdx.x * blockDim.x + threadIdx.x;
    if (e < EE) atomicAdd(&g_cnt[dst[e]], 1);
}

__global__ void k_scan1() {  // per-1024 block inclusive scan of g_cnt -> g_incl, block sums
    __shared__ int s[1024];
    int g = blockIdx.x * 1024 + threadIdx.x;
    int v = (g < NN) ? g_cnt[g] : 0;
    s[threadIdx.x] = v;
    __syncthreads();
    for (int off = 1; off < 1024; off <<= 1) {
        int t = (threadIdx.x >= off) ? s[threadIdx.x - off] : 0;
        __syncthreads();
        s[threadIdx.x] += t;
        __syncthreads();
    }
    if (g < NN) g_incl[g] = s[threadIdx.x];
    if (threadIdx.x == 1023) g_bsum[blockIdx.x] = s[1023];
}

__global__ void k_scan2(int nb) {  // serial exclusive scan of block sums (tiny)
    if (threadIdx.x == 0 && blockIdx.x == 0) {
        int a = 0;
        for (int i = 0; i < nb; i++) { int t = g_bsum[i]; g_bsum[i] = a; a += t; }
    }
}

__global__ void k_scan3() {
    int g = blockIdx.x * blockDim.x + threadIdx.x;
    if (g < NN) {
        int rs = g_incl[g] + g_bsum[g >> 10] - g_cnt[g];
        g_rowstart[g] = rs;
        g_fill[g] = rs;
        g_inv[g] = rsqrtf((float)g_cnt[g] + 1.0f);
    }
}

__global__ void k_scatter(const int* __restrict__ src, const int* __restrict__ dst) {
    int e = blockIdx.x * blockDim.x + threadIdx.x;
    if (e < EE) {
        int p = atomicAdd(&g_fill[dst[e]], 1);
        g_csr[p] = src[e];
    }
}

// ---------------- GCN propagation: Y[i] = inv[i]*(inv[i]*X[i] + sum inv[s]*X[s]) ---
template <int F>
__global__ void k_prop(const float* __restrict__ X, float* __restrict__ Y) {
    int i = blockIdx.x;
    int f = threadIdx.x;  // blockDim == F
    float invi = g_inv[i];
    float acc = invi * X[(size_t)i * F + f];
    int beg = g_rowstart[i];
    int end = beg + g_cnt[i];
    int j = beg;
    for (; j + 1 < end; j += 2) {
        int s0 = g_csr[j], s1 = g_csr[j + 1];
        float a0 = g_inv[s0] * X[(size_t)s0 * F + f];
        float a1 = g_inv[s1] * X[(size_t)s1 * F + f];
        acc += a0 + a1;
    }
    if (j < end) {
        int s0 = g_csr[j];
        acc += g_inv[s0] * X[(size_t)s0 * F + f];
    }
    Y[(size_t)i * F + f] = invi * acc;
}

// ---------------- 3xTF32 tensor-core GEMM -------------------------------------
// C[M,N] = A[M,K] @ B[K,N] + bias, optional relu. A,B,C row-major.
// Block tile 128x128x32, 512 threads = 16 warps in 4x4 grid, warp tile 32x32.
#define GBM 128
#define GBN 128
#define GBK 32
#define APAD 4   // stride 36 ≡ 4 (mod 32): frag reads conflict-free
#define BPAD 8   // stride 136 ≡ 8 (mod 32): frag reads conflict-free

__device__ __forceinline__ void tf32_split(float v, uint32_t& hi, uint32_t& lo) {
    uint32_t h;
    asm("cvt.rna.tf32.f32 %0, %1;" : "=r"(h) : "f"(v));
    float r = v - __uint_as_float(h);
    uint32_t l;
    asm("cvt.rna.tf32.f32 %0, %1;" : "=r"(l) : "f"(r));
    hi = h; lo = l;
}

__device__ __forceinline__ void mma_tf32(float c[4], uint32_t a0, uint32_t a1,
                                         uint32_t a2, uint32_t a3,
                                         uint32_t b0, uint32_t b1) {
    asm volatile(
        "mma.sync.aligned.m16n8k8.row.col.f32.tf32.tf32.f32 "
        "{%0,%1,%2,%3}, {%4,%5,%6,%7}, {%8,%9}, {%0,%1,%2,%3};"
        : "+f"(c[0]), "+f"(c[1]), "+f"(c[2]), "+f"(c[3])
        : "r"(a0), "r"(a1), "r"(a2), "r"(a3), "r"(b0), "r"(b1));
}

__global__ __launch_bounds__(512, 1) void k_gemm_tc(
    const float* __restrict__ A, const float* __restrict__ B,
    const float* __restrict__ bias, float* __restrict__ C,
    int M, int N, int K, int doRelu) {
    __shared__ float As[GBM][GBK + APAD];   // [m][k]
    __shared__ float Bs[GBK][GBN + BPAD];   // [k][n]

    int tid = threadIdx.x;
    int warp = tid >> 5;
    int lane = tid & 31;
    int gid = lane >> 2;   // groupID 0..7
    int tig = lane & 3;    // thread-in-group 0..3
    int wm = warp >> 2;    // 0..3
    int wn = warp & 3;     // 0..3

    int m0 = blockIdx.y * GBM;
    int n0 = blockIdx.x * GBN;

    float acc[2][4][4];
#pragma unroll
    for (int mt = 0; mt < 2; mt++)
#pragma unroll
        for (int nt = 0; nt < 4; nt++)
#pragma unroll
            for (int r = 0; r < 4; r++) acc[mt][nt][r] = 0.0f;

    // global load indices
    int a_r = tid >> 3;           // 0..63 (two passes: +64)
    int a_c = (tid & 7) * 4;      // k col within tile
    int b_r = tid >> 5;           // 0..15 (two passes: +16)
    int b_c = (tid & 31) * 4;     // n col within tile

    for (int k0 = 0; k0 < K; k0 += GBK) {
        // load A tile (guard M edge)
#pragma unroll
        for (int p = 0; p < 2; p++) {
            int mr = a_r + p * 64;
            int m = m0 + mr;
            float4 v = make_float4(0.f, 0.f, 0.f, 0.f);
            if (m < M) v = *(const float4*)&A[(size_t)m * K + k0 + a_c];
            As[mr][a_c + 0] = v.x;
            As[mr][a_c + 1] = v.y;
            As[mr][a_c + 2] = v.z;
            As[mr][a_c + 3] = v.w;
        }
        // load B tile (K,N always divisible)
#pragma unroll
        for (int p = 0; p < 2; p++) {
            int kr = b_r + p * 16;
            float4 v = *(const float4*)&B[(size_t)(k0 + kr) * N + n0 + b_c];
            Bs[kr][b_c + 0] = v.x;
            Bs[kr][b_c + 1] = v.y;
            Bs[kr][b_c + 2] = v.z;
            Bs[kr][b_c + 3] = v.w;
        }
        __syncthreads();

#pragma unroll
        for (int ks = 0; ks < GBK / 8; ks++) {
            // A fragments (2 m-tiles), hi/lo
            uint32_t ah[2][4], al[2][4];
#pragma unroll
            for (int mt = 0; mt < 2; mt++) {
                int rm = wm * 32 + mt * 16;
                int kc = ks * 8 + tig;
                float f0 = As[rm + gid][kc];
                float f1 = As[rm + gid + 8][kc];
                float f2 = As[rm + gid][kc + 4];
                float f3 = As[rm + gid + 8][kc + 4];
                tf32_split(f0, ah[mt][0], al[mt][0]);
                tf32_split(f1, ah[mt][1], al[mt][1]);
                tf32_split(f2, ah[mt][2], al[mt][2]);
                tf32_split(f3, ah[mt][3], al[mt][3]);
            }
            // B fragments (4 n-tiles), hi/lo
            uint32_t bh[4][2], bl[4][2];
#pragma unroll
            for (int nt = 0; nt < 4; nt++) {
                int cn = wn * 32 + nt * 8 + gid;
                float f0 = Bs[ks * 8 + tig][cn];
                float f1 = Bs[ks * 8 + tig + 4][cn];
                tf32_split(f0, bh[nt][0], bl[nt][0]);
                tf32_split(f1, bh[nt][1], bl[nt][1]);
            }
#pragma unroll
            for (int mt = 0; mt < 2; mt++)
#pragma unroll
                for (int nt = 0; nt < 4; nt++) {
                    mma_tf32(acc[mt][nt], ah[mt][0], ah[mt][1], ah[mt][2], ah[mt][3],
                             bl[nt][0], bl[nt][1]);
                    mma_tf32(acc[mt][nt], al[mt][0], al[mt][1], al[mt][2], al[mt][3],
                             bh[nt][0], bh[nt][1]);
                    mma_tf32(acc[mt][nt], ah[mt][0], ah[mt][1], ah[mt][2], ah[mt][3],
                             bh[nt][0], bh[nt][1]);
                }
        }
        __syncthreads();
    }

    // epilogue: bias (+relu), guarded stores
#pragma unroll
    for (int mt = 0; mt < 2; mt++) {
        int rbase = m0 + wm * 32 + mt * 16 + gid;
#pragma unroll
        for (int nt = 0; nt < 4; nt++) {
            int c0 = n0 + wn * 32 + nt * 8 + tig * 2;
            float bia0 = bias[c0], bia1 = bias[c0 + 1];
#pragma unroll
            for (int half = 0; half < 2; half++) {
                int m = rbase + half * 8;
                if (m >= M) continue;
                float v0 = acc[mt][nt][half * 2 + 0] + bia0;
                float v1 = acc[mt][nt][half * 2 + 1] + bia1;
                if (doRelu) { v0 = fmaxf(v0, 0.f); v1 = fmaxf(v1, 0.f); }
                C[(size_t)m * N + c0] = v0;
                C[(size_t)m * N + c0 + 1] = v1;
            }
        }
    }
}

// ---------------- softmax(relu(h3)) row-wise + argmax -------------------------
__global__ __launch_bounds__(512) void k_softmax(const float* __restrict__ H,
                                                 float* __restrict__ S) {
    __shared__ float sv[512];
    __shared__ int si[512];
    int i = blockIdx.x, c = threadIdx.x;
    float z = fmaxf(H[(size_t)i * CC + c], 0.0f);
    sv[c] = z; si[c] = c;
    __syncthreads();
    for (int off = 256; off > 0; off >>= 1) {
        if (c < off) {
            float v2 = sv[c + off]; int i2 = si[c + off];
            if (v2 > sv[c] || (v2 == sv[c] && i2 < si[c])) { sv[c] = v2; si[c] = i2; }
        }
        __syncthreads();
    }
    float m = sv[0]; int am = si[0];
    __syncthreads();
    float e = expf(z - m);
    sv[c] = e;
    __syncthreads();
    for (int off = 256; off > 0; off >>= 1) {
        if (c < off) sv[c] += sv[c + off];
        __syncthreads();
    }
    float invsum = 1.0f / sv[0];
    S[(size_t)i * CC + c] = e * invsum;
    if (c == 0) g_cluster[i] = am;
}

// ---------------- score layer ------------------------------------------------
__global__ void k_hs(const float* __restrict__ x, const float* __restrict__ Ws) {
    int t = blockIdx.x * blockDim.x + threadIdx.x;
    int w = t >> 5, lane = t & 31;
    if (w >= NN) return;
    float a = 0.0f;
#pragma unroll
    for (int r = 0; r < 4; r++) {
        int f = lane + 32 * r;
        a += x[(size_t)w * FF + f] * Ws[f];
    }
#pragma unroll
    for (int off = 16; off > 0; off >>= 1) a += __shfl_down_sync(0xFFFFFFFFu, a, off);
    if (lane == 0) g_hs[w] = a;
}

__global__ void k_intra() {  // per node: count intra in-edges; mark cluster nonempty
    int t = blockIdx.x * blockDim.x + threadIdx.x;
    int i = t >> 5, lane = t & 31;
    if (i >= NN) return;
    int myc = g_cluster[i];
    int beg = g_rowstart[i], end = beg + g_cnt[i];
    int cint = 0;
    for (int j = beg + lane; j < end; j += 32)
        cint += (g_cluster[g_csr[j]] == myc) ? 1 : 0;
#pragma unroll
    for (int off = 16; off > 0; off >>= 1) cint += __shfl_down_sync(0xFFFFFFFFu, cint, off);
    if (lane == 0) {
        g_invs[i] = rsqrtf((float)cint + 1.0f);
        if (cint > 0) atomicOr(&g_nonempty[myc], 1);
    }
}

__global__ void k_score(const float* __restrict__ bs) {
    int t = blockIdx.x * blockDim.x + threadIdx.x;
    int i = t >> 5, lane = t & 31;
    if (i >= NN) return;
    int myc = g_cluster[i];
    int beg = g_rowstart[i], end = beg + g_cnt[i];
    float acc = 0.0f;
    for (int j = beg + lane; j < end; j += 32) {
        int s = g_csr[j];
        if (g_cluster[s] == myc) acc += g_invs[s] * g_hs[s];
    }
#pragma unroll
    for (int off = 16; off > 0; off >>= 1) acc += __shfl_down_sync(0xFFFFFFFFu, acc, off);
    if (lane == 0) {
        float invi = g_invs[i];
        float agg = invi * (acc + invi * g_hs[i]);
        g_score[i] = tanhf(agg + bs[0]);
    }
}

__global__ void k_segmax() {
    int i = blockIdx.x * blockDim.x + threadIdx.x;
    if (i < NN) atomicMax(&g_cmaxkey[g_cluster[i]], fkey(g_score[i]));
}

__global__ void k_argidx() {
    int i = blockIdx.x * blockDim.x + threadIdx.x;
    if (i < NN && fkey(g_score[i]) >= g_cmaxkey[g_cluster[i]])
        atomicMin(&g_idx[g_cluster[i]], i);
}

// ---------------- outputs ----------------------------------------------------
__global__ void k_newx(const float* __restrict__ x, float* __restrict__ out) {
    int c = blockIdx.x, f = threadIdx.x;  // CC blocks x FF threads
    float v = 0.0f;
    if (g_nonempty[c]) {
        float alpha = fdec(g_cmaxkey[c]);
        int id = g_idx[c];
        v = x[(size_t)id * FF + f] * alpha;
    }
    out[(size_t)c * FF + f] = v;
}

__global__ void k_zero(float* __restrict__ p, int n) {
    int i = blockIdx.x * blockDim.x + threadIdx.x;
    if (i < n) p[i] = 0.0f;
}

__global__ void k_adj(const int* __restrict__ src, const int* __restrict__ dst,
                      float* __restrict__ adj) {
    int e = blockIdx.x * blockDim.x + threadIdx.x;
    if (e >= EE) return;
    int ci = g_cluster[src[e]], cj = g_cluster[dst[e]];
    if (ci != cj && g_nonempty[ci] && g_nonempty[cj]) adj[ci * CC + cj] = 1.0f;
}

// ---------------- host -------------------------------------------------------
extern "C" void kernel_launch(void* const* d_in, const int* in_sizes, int n_in,
                              void* d_out, int out_size) {
    const float* x  = (const float*)d_in[0];
    const int*   ei = (const int*)d_in[1];
    const int*   src = ei;
    const int*   dst = ei + EE;
    const float* W1 = (const float*)d_in[3];
    const float* b1 = (const float*)d_in[4];
    const float* W2 = (const float*)d_in[5];
    const float* b2 = (const float*)d_in[6];
    const float* W3 = (const float*)d_in[7];
    const float* b3 = (const float*)d_in[8];
    const float* Ws = (const float*)d_in[9];
    const float* bs = (const float*)d_in[10];

    float* out      = (float*)d_out;
    float* out_newx = out;
    float* out_adj  = out + (size_t)CC * FF;
    float* out_S    = out + (size_t)CC * FF + (size_t)CC * CC + CC;

    float *pP, *ph, *ph3;
    cudaGetSymbolAddress((void**)&pP,  g_P);
    cudaGetSymbolAddress((void**)&ph,  g_h);
    cudaGetSymbolAddress((void**)&ph3, g_h3);

    const int TB = 256;
    int gN = (NN + TB - 1) / TB;
    int gE = (EE + TB - 1) / TB;
    int gW = (NN * 32 + TB - 1) / TB;  // warp-per-node kernels
    int nbScan = (NN + 1023) / 1024;

    // graph build (CSR) + degree normalization
    k_init<<<gN, TB>>>();
    k_count<<<gE, TB>>>(dst);
    k_scan1<<<nbScan, 1024>>>();
    k_scan2<<<1, 32>>>(nbScan);
    k_scan3<<<gN, TB>>>();
    k_scatter<<<gE, TB>>>(src, dst);

    // 3-layer GCN (propagate in input space, then tensor-core linear+bias+relu)
    dim3 gemmGrid1(HH / GBN, (NN + GBM - 1) / GBM);
    dim3 gemmGrid3(CC / GBN, (NN + GBM - 1) / GBM);
    k_prop<FF><<<NN, FF>>>(x, pP);
    k_gemm_tc<<<gemmGrid1, 512>>>(pP, W1, b1, ph, NN, HH, FF, 1);
    k_prop<HH><<<NN, HH>>>(ph, pP);
    k_gemm_tc<<<gemmGrid1, 512>>>(pP, W2, b2, ph, NN, HH, HH, 1);
    k_prop<HH><<<NN, HH>>>(ph, pP);
    k_gemm_tc<<<gemmGrid3, 512>>>(pP, W3, b3, ph3, NN, CC, HH, 0);

    // softmax(relu) -> S output + hard clusters
    k_softmax<<<NN, 512>>>(ph3, out_S);

    // score layer on intra-cluster subgraph
    k_hs<<<gW, TB>>>(x, Ws);
    k_intra<<<gW, TB>>>();
    k_score<<<gW, TB>>>(bs);
    k_segmax<<<gN, TB>>>();
    k_argidx<<<gN, TB>>>();

    // pooled outputs: new_x, new_adj, new_batch (batch is all zeros)
    k_newx<<<CC, FF>>>(x, out_newx);
    int zn = CC * CC + CC;  // adjacency + new_batch region
    k_zero<<<(zn + TB - 1) / TB, TB>>>(out_adj, zn);
    k_adj<<<gE, TB>>>(src, dst, out_adj);
}

// round 6
// speedup vs baseline: 2.1320x; 1.3347x over previous
#include <cuda_runtime.h>
#include <math.h>
#include <stdint.h>

#define NN 50000
#define FF 128
#define HH 256
#define CC 512
#define EE 800000

// ---------------- scratch (device globals; no allocation allowed) -------------
__device__ int      g_cnt[NN];
__device__ int      g_rowstart[NN];
__device__ int      g_fill[NN];
__device__ int      g_incl[NN];
__device__ int      g_bsum[64];
__device__ int      g_csr[EE];
__device__ float    g_inv[NN];
__device__ float    g_hs[NN];
__device__ float    g_invs[NN];
__device__ float    g_score[NN];
__device__ int      g_cluster[NN];
__device__ unsigned g_cmaxkey[CC];
__device__ int      g_idx[CC];
__device__ int      g_nonempty[CC];
__device__ float    g_P[(size_t)NN * HH];   // propagation output (<=256 feats)
__device__ float    g_h[(size_t)NN * HH];   // hidden activations
__device__ float    g_h3[(size_t)NN * CC];  // layer-3 pre-softmax

// monotonic float<->uint key for atomicMax on floats
__device__ __forceinline__ unsigned fkey(float f) {
    unsigned u = __float_as_uint(f);
    return (u & 0x80000000u) ? ~u : (u | 0x80000000u);
}
__device__ __forceinline__ float fdec(unsigned k) {
    return (k & 0x80000000u) ? __uint_as_float(k ^ 0x80000000u)
                             : __uint_as_float(~k);
}

// ---------------- setup kernels ----------------------------------------------
__global__ void k_init() {
    int i = blockIdx.x * blockDim.x + threadIdx.x;
    if (i < NN) g_cnt[i] = 0;
    if (i < CC) { g_cmaxkey[i] = 0u; g_idx[i] = 0x7FFFFFFF; g_nonempty[i] = 0; }
}

__global__ void k_count(const int* __restrict__ dst) {
    int e = blockIdx.x * blockDim.x + threadIdx.x;
    if (e < EE) atomicAdd(&g_cnt[dst[e]], 1);
}

__global__ void k_scan1() {  // per-1024 block inclusive scan of g_cnt -> g_incl, block sums
    __shared__ int s[1024];
    int g = blockIdx.x * 1024 + threadIdx.x;
    int v = (g < NN) ? g_cnt[g] : 0;
    s[threadIdx.x] = v;
    __syncthreads();
    for (int off = 1; off < 1024; off <<= 1) {
        int t = (threadIdx.x >= off) ? s[threadIdx.x - off] : 0;
        __syncthreads();
        s[threadIdx.x] += t;
        __syncthreads();
    }
    if (g < NN) g_incl[g] = s[threadIdx.x];
    if (threadIdx.x == 1023) g_bsum[blockIdx.x] = s[1023];
}

__global__ void k_scan2(int nb) {  // serial exclusive scan of block sums (tiny)
    if (threadIdx.x == 0 && blockIdx.x == 0) {
        int a = 0;
        for (int i = 0; i < nb; i++) { int t = g_bsum[i]; g_bsum[i] = a; a += t; }
    }
}

__global__ void k_scan3() {
    int g = blockIdx.x * blockDim.x + threadIdx.x;
    if (g < NN) {
        int rs = g_incl[g] + g_bsum[g >> 10] - g_cnt[g];
        g_rowstart[g] = rs;
        g_fill[g] = rs;
        g_inv[g] = rsqrtf((float)g_cnt[g] + 1.0f);
    }
}

__global__ void k_scatter(const int* __restrict__ src, const int* __restrict__ dst) {
    int e = blockIdx.x * blockDim.x + threadIdx.x;
    if (e < EE) {
        int p = atomicAdd(&g_fill[dst[e]], 1);
        g_csr[p] = src[e];
    }
}

// ------- GCN propagation, warp-per-node, float4: Y[i]=inv[i]*(inv[i]X[i]+sum inv[s]X[s])
template <int F>
__global__ __launch_bounds__(256) void k_prop(const float* __restrict__ X,
                                              float* __restrict__ Y) {
    constexpr int V = F / 128;  // float4 per lane (1 for F=128, 2 for F=256)
    int w = blockIdx.x * (blockDim.x >> 5) + (threadIdx.x >> 5);
    int lane = threadIdx.x & 31;
    if (w >= NN) return;
    float invi = g_inv[w];
    const float4* Xw = (const float4*)(X + (size_t)w * F);
    float4 acc[V];
#pragma unroll
    for (int v = 0; v < V; v++) {
        float4 t = Xw[lane + v * 32];
        acc[v] = make_float4(invi * t.x, invi * t.y, invi * t.z, invi * t.w);
    }
    int beg = g_rowstart[w];
    int end = beg + g_cnt[w];
    int j = beg;
    for (; j + 4 <= end; j += 4) {
        int s0 = g_csr[j], s1 = g_csr[j + 1], s2 = g_csr[j + 2], s3 = g_csr[j + 3];
        float w0 = g_inv[s0], w1 = g_inv[s1], w2 = g_inv[s2], w3 = g_inv[s3];
        const float4* r0 = (const float4*)(X + (size_t)s0 * F);
        const float4* r1 = (const float4*)(X + (size_t)s1 * F);
        const float4* r2 = (const float4*)(X + (size_t)s2 * F);
        const float4* r3 = (const float4*)(X + (size_t)s3 * F);
#pragma unroll
        for (int v = 0; v < V; v++) {
            float4 t0 = r0[lane + v * 32];
            float4 t1 = r1[lane + v * 32];
            float4 t2 = r2[lane + v * 32];
            float4 t3 = r3[lane + v * 32];
            acc[v].x += w0 * t0.x + w1 * t1.x + w2 * t2.x + w3 * t3.x;
            acc[v].y += w0 * t0.y + w1 * t1.y + w2 * t2.y + w3 * t3.y;
            acc[v].z += w0 * t0.z + w1 * t1.z + w2 * t2.z + w3 * t3.z;
            acc[v].w += w0 * t0.w + w1 * t1.w + w2 * t2.w + w3 * t3.w;
        }
    }
    for (; j < end; j++) {
        int s0 = g_csr[j];
        float w0 = g_inv[s0];
        const float4* r0 = (const float4*)(X + (size_t)s0 * F);
#pragma unroll
        for (int v = 0; v < V; v++) {
            float4 t0 = r0[lane + v * 32];
            acc[v].x += w0 * t0.x; acc[v].y += w0 * t0.y;
            acc[v].z += w0 * t0.z; acc[v].w += w0 * t0.w;
        }
    }
    float4* Yw = (float4*)(Y + (size_t)w * F);
#pragma unroll
    for (int v = 0; v < V; v++) {
        Yw[lane + v * 32] = make_float4(invi * acc[v].x, invi * acc[v].y,
                                        invi * acc[v].z, invi * acc[v].w);
    }
}

// ---------------- 3xTF32 tensor-core GEMM, split-once + double buffered -------
// C[M,N] = A[M,K] @ B[K,N] + bias, optional relu. A,B,C row-major.
// Block tile 128x128x32, 512 threads = 16 warps (4x4), warp tile 32x32.
// SMEM holds pre-split hi/lo tf32 tiles; ping-pong buffers overlap G-loads.
#define GBM 128
#define GBN 128
#define GBK 32
#define ASTR 36    // GBK+4: stride ≡ 4 (mod 32) -> conflict-free frag reads
#define BSTR 136   // GBN+8: stride ≡ 8 (mod 32) -> conflict-free frag reads
#define ASZ (GBM * ASTR)
#define BSZ (GBK * BSTR)
#define BUFSZ (2 * ASZ + 2 * BSZ)
#define GEMM_SMEM_BYTES (2 * BUFSZ * 4)

__device__ __forceinline__ void tf32_split(float v, uint32_t& hi, uint32_t& lo) {
    uint32_t h;
    asm("cvt.rna.tf32.f32 %0, %1;" : "=r"(h) : "f"(v));
    float r = v - __uint_as_float(h);
    uint32_t l;
    asm("cvt.rna.tf32.f32 %0, %1;" : "=r"(l) : "f"(r));
    hi = h; lo = l;
}

__device__ __forceinline__ void mma_tf32(float c[4], uint32_t a0, uint32_t a1,
                                         uint32_t a2, uint32_t a3,
                                         uint32_t b0, uint32_t b1) {
    asm volatile(
        "mma.sync.aligned.m16n8k8.row.col.f32.tf32.tf32.f32 "
        "{%0,%1,%2,%3}, {%4,%5,%6,%7}, {%8,%9}, {%0,%1,%2,%3};"
        : "+f"(c[0]), "+f"(c[1]), "+f"(c[2]), "+f"(c[3])
        : "r"(a0), "r"(a1), "r"(a2), "r"(a3), "r"(b0), "r"(b1));
}

__global__ __launch_bounds__(512, 1) void k_gemm_tc(
    const float* __restrict__ A, const float* __restrict__ B,
    const float* __restrict__ bias, float* __restrict__ C,
    int M, int N, int K, int doRelu) {
    extern __shared__ float smem[];

    int tid = threadIdx.x;
    int warp = tid >> 5;
    int lane = tid & 31;
    int gid = lane >> 2;   // groupID 0..7
    int tig = lane & 3;    // thread-in-group 0..3
    int wm = warp >> 2;    // 0..3
    int wn = warp & 3;     // 0..3

    int m0 = blockIdx.y * GBM;
    int n0 = blockIdx.x * GBN;

    float acc[2][4][4];
#pragma unroll
    for (int mt = 0; mt < 2; mt++)
#pragma unroll
        for (int nt = 0; nt < 4; nt++)
#pragma unroll
            for (int r = 0; r < 4; r++) acc[mt][nt][r] = 0.0f;

    // global load indices
    int a_r = tid >> 3;           // 0..63 (two passes: +64)
    int a_c = (tid & 7) * 4;      // k col within tile
    int b_r = tid >> 5;           // 0..15 (two passes: +16)
    int b_c = (tid & 31) * 4;     // n col within tile

    float4 arv[2], brv[2];

    auto loadG = [&](int t) {
        int k0 = t * GBK;
#pragma unroll
        for (int p = 0; p < 2; p++) {
            int m = m0 + a_r + p * 64;
            arv[p] = make_float4(0.f, 0.f, 0.f, 0.f);
            if (m < M) arv[p] = *(const float4*)&A[(size_t)m * K + k0 + a_c];
        }
#pragma unroll
        for (int p = 0; p < 2; p++) {
            int kr = b_r + p * 16;
            brv[p] = *(const float4*)&B[(size_t)(k0 + kr) * N + n0 + b_c];
        }
    };

    auto storeSplit = [&](int buf) {
        float* Ah = smem + buf * BUFSZ;
        float* Al = Ah + ASZ;
        float* Bh = Al + ASZ;
        float* Bl = Bh + BSZ;
#pragma unroll
        for (int p = 0; p < 2; p++) {
            int mr = a_r + p * 64;
            float vv[4] = {arv[p].x, arv[p].y, arv[p].z, arv[p].w};
            float hv[4], lv[4];
#pragma unroll
            for (int i = 0; i < 4; i++) {
                uint32_t h, l;
                tf32_split(vv[i], h, l);
                hv[i] = __uint_as_float(h);
                lv[i] = __uint_as_float(l);
            }
            *(float4*)&Ah[mr * ASTR + a_c] = make_float4(hv[0], hv[1], hv[2], hv[3]);
            *(float4*)&Al[mr * ASTR + a_c] = make_float4(lv[0], lv[1], lv[2], lv[3]);
        }
#pragma unroll
        for (int p = 0; p < 2; p++) {
            int kr = b_r + p * 16;
            float vv[4] = {brv[p].x, brv[p].y, brv[p].z, brv[p].w};
            float hv[4], lv[4];
#pragma unroll
            for (int i = 0; i < 4; i++) {
                uint32_t h, l;
                tf32_split(vv[i], h, l);
                hv[i] = __uint_as_float(h);
                lv[i] = __uint_as_float(l);
            }
            *(float4*)&Bh[kr * BSTR + b_c] = make_float4(hv[0], hv[1], hv[2], hv[3]);
            *(float4*)&Bl[kr * BSTR + b_c] = make_float4(lv[0], lv[1], lv[2], lv[3]);
        }
    };

    auto compute = [&](int buf) {
        const float* Ah = smem + buf * BUFSZ;
        const float* Al = Ah + ASZ;
        const float* Bh = Al + ASZ;
        const float* Bl = Bh + BSZ;
#pragma unroll
        for (int ks = 0; ks < GBK / 8; ks++) {
            uint32_t ah[2][4], al[2][4];
#pragma unroll
            for (int mt = 0; mt < 2; mt++) {
                int rm = wm * 32 + mt * 16;
                int kc = ks * 8 + tig;
                ah[mt][0] = __float_as_uint(Ah[(rm + gid) * ASTR + kc]);
                ah[mt][1] = __float_as_uint(Ah[(rm + gid + 8) * ASTR + kc]);
                ah[mt][2] = __float_as_uint(Ah[(rm + gid) * ASTR + kc + 4]);
                ah[mt][3] = __float_as_uint(Ah[(rm + gid + 8) * ASTR + kc + 4]);
                al[mt][0] = __float_as_uint(Al[(rm + gid) * ASTR + kc]);
                al[mt][1] = __float_as_uint(Al[(rm + gid + 8) * ASTR + kc]);
                al[mt][2] = __float_as_uint(Al[(rm + gid) * ASTR + kc + 4]);
                al[mt][3] = __float_as_uint(Al[(rm + gid + 8) * ASTR + kc + 4]);
            }
            uint32_t bh[4][2], bl[4][2];
#pragma unroll
            for (int nt = 0; nt < 4; nt++) {
                int cn = wn * 32 + nt * 8 + gid;
                bh[nt][0] = __float_as_uint(Bh[(ks * 8 + tig) * BSTR + cn]);
                bh[nt][1] = __float_as_uint(Bh[(ks * 8 + tig + 4) * BSTR + cn]);
                bl[nt][0] = __float_as_uint(Bl[(ks * 8 + tig) * BSTR + cn]);
                bl[nt][1] = __float_as_uint(Bl[(ks * 8 + tig + 4) * BSTR + cn]);
            }
#pragma unroll
            for (int mt = 0; mt < 2; mt++)
#pragma unroll
                for (int nt = 0; nt < 4; nt++) {
                    mma_tf32(acc[mt][nt], ah[mt][0], ah[mt][1], ah[mt][2], ah[mt][3],
                             bl[nt][0], bl[nt][1]);
                    mma_tf32(acc[mt][nt], al[mt][0], al[mt][1], al[mt][2], al[mt][3],
                             bh[nt][0], bh[nt][1]);
                    mma_tf32(acc[mt][nt], ah[mt][0], ah[mt][1], ah[mt][2], ah[mt][3],
                             bh[nt][0], bh[nt][1]);
                }
        }
    };

    int T = K / GBK;
    loadG(0);
    storeSplit(0);
    __syncthreads();
    for (int t = 0; t < T; t++) {
        int buf = t & 1;
        bool more = (t + 1 < T);
        if (more) loadG(t + 1);
        compute(buf);
        if (more) storeSplit(buf ^ 1);
        __syncthreads();
    }

    // epilogue: bias (+relu), guarded stores
#pragma unroll
    for (int mt = 0; mt < 2; mt++) {
        int rbase = m0 + wm * 32 + mt * 16 + gid;
#pragma unroll
        for (int nt = 0; nt < 4; nt++) {
            int c0 = n0 + wn * 32 + nt * 8 + tig * 2;
            float bia0 = bias[c0], bia1 = bias[c0 + 1];
#pragma unroll
            for (int half = 0; half < 2; half++) {
                int m = rbase + half * 8;
                if (m >= M) continue;
                float v0 = acc[mt][nt][half * 2 + 0] + bia0;
                float v1 = acc[mt][nt][half * 2 + 1] + bia1;
                if (doRelu) { v0 = fmaxf(v0, 0.f); v1 = fmaxf(v1, 0.f); }
                C[(size_t)m * N + c0] = v0;
                C[(size_t)m * N + c0 + 1] = v1;
            }
        }
    }
}

// ---------------- softmax(relu(h3)) row-wise + argmax -------------------------
__global__ __launch_bounds__(512) void k_softmax(const float* __restrict__ H,
                                                 float* __restrict__ S) {
    __shared__ float sv[512];
    __shared__ int si[512];
    int i = blockIdx.x, c = threadIdx.x;
    float z = fmaxf(H[(size_t)i * CC + c], 0.0f);
    sv[c] = z; si[c] = c;
    __syncthreads();
    for (int off = 256; off > 0; off >>= 1) {
        if (c < off) {
            float v2 = sv[c + off]; int i2 = si[c + off];
            if (v2 > sv[c] || (v2 == sv[c] && i2 < si[c])) { sv[c] = v2; si[c] = i2; }
        }
        __syncthreads();
    }
    float m = sv[0]; int am = si[0];
    __syncthreads();
    float e = expf(z - m);
    sv[c] = e;
    __syncthreads();
    for (int off = 256; off > 0; off >>= 1) {
        if (c < off) sv[c] += sv[c + off];
        __syncthreads();
    }
    float invsum = 1.0f / sv[0];
    S[(size_t)i * CC + c] = e * invsum;
    if (c == 0) g_cluster[i] = am;
}

// ---------------- score layer ------------------------------------------------
__global__ void k_hs(const float* __restrict__ x, const float* __restrict__ Ws) {
    int t = blockIdx.x * blockDim.x + threadIdx.x;
    int w = t >> 5, lane = t & 31;
    if (w >= NN) return;
    float a = 0.0f;
#pragma unroll
    for (int r = 0; r < 4; r++) {
        int f = lane + 32 * r;
        a += x[(size_t)w * FF + f] * Ws[f];
    }
#pragma unroll
    for (int off = 16; off > 0; off >>= 1) a += __shfl_down_sync(0xFFFFFFFFu, a, off);
    if (lane == 0) g_hs[w] = a;
}

__global__ void k_intra() {  // per node: count intra in-edges; mark cluster nonempty
    int t = blockIdx.x * blockDim.x + threadIdx.x;
    int i = t >> 5, lane = t & 31;
    if (i >= NN) return;
    int myc = g_cluster[i];
    int beg = g_rowstart[i], end = beg + g_cnt[i];
    int cint = 0;
    for (int j = beg + lane; j < end; j += 32)
        cint += (g_cluster[g_csr[j]] == myc) ? 1 : 0;
#pragma unroll
    for (int off = 16; off > 0; off >>= 1) cint += __shfl_down_sync(0xFFFFFFFFu, cint, off);
    if (lane == 0) {
        g_invs[i] = rsqrtf((float)cint + 1.0f);
        if (cint > 0) atomicOr(&g_nonempty[myc], 1);
    }
}

__global__ void k_score(const float* __restrict__ bs) {
    int t = blockIdx.x * blockDim.x + threadIdx.x;
    int i = t >> 5, lane = t & 31;
    if (i >= NN) return;
    int myc = g_cluster[i];
    int beg = g_rowstart[i], end = beg + g_cnt[i];
    float acc = 0.0f;
    for (int j = beg + lane; j < end; j += 32) {
        int s = g_csr[j];
        if (g_cluster[s] == myc) acc += g_invs[s] * g_hs[s];
    }
#pragma unroll
    for (int off = 16; off > 0; off >>= 1) acc += __shfl_down_sync(0xFFFFFFFFu, acc, off);
    if (lane == 0) {
        float invi = g_invs[i];
        float agg = invi * (acc + invi * g_hs[i]);
        g_score[i] = tanhf(agg + bs[0]);
    }
}

__global__ void k_segmax() {
    int i = blockIdx.x * blockDim.x + threadIdx.x;
    if (i < NN) atomicMax(&g_cmaxkey[g_cluster[i]], fkey(g_score[i]));
}

__global__ void k_argidx() {
    int i = blockIdx.x * blockDim.x + threadIdx.x;
    if (i < NN && fkey(g_score[i]) >= g_cmaxkey[g_cluster[i]])
        atomicMin(&g_idx[g_cluster[i]], i);
}

// ---------------- outputs ----------------------------------------------------
__global__ void k_newx(const float* __restrict__ x, float* __restrict__ out) {
    int c = blockIdx.x, f = threadIdx.x;  // CC blocks x FF threads
    float v = 0.0f;
    if (g_nonempty[c]) {
        float alpha = fdec(g_cmaxkey[c]);
        int id = g_idx[c];
        v = x[(size_t)id * FF + f] * alpha;
    }
    out[(size_t)c * FF + f] = v;
}

__global__ void k_zero(float* __restrict__ p, int n) {
    int i = blockIdx.x * blockDim.x + threadIdx.x;
    if (i < n) p[i] = 0.0f;
}

__global__ void k_adj(const int* __restrict__ src, const int* __restrict__ dst,
                      float* __restrict__ adj) {
    int e = blockIdx.x * blockDim.x + threadIdx.x;
    if (e >= EE) return;
    int ci = g_cluster[src[e]], cj = g_cluster[dst[e]];
    if (ci != cj && g_nonempty[ci] && g_nonempty[cj]) adj[ci * CC + cj] = 1.0f;
}

// ---------------- host -------------------------------------------------------
extern "C" void kernel_launch(void* const* d_in, const int* in_sizes, int n_in,
                              void* d_out, int out_size) {
    const float* x  = (const float*)d_in[0];
    const int*   ei = (const int*)d_in[1];
    const int*   src = ei;
    const int*   dst = ei + EE;
    const float* W1 = (const float*)d_in[3];
    const float* b1 = (const float*)d_in[4];
    const float* W2 = (const float*)d_in[5];
    const float* b2 = (const float*)d_in[6];
    const float* W3 = (const float*)d_in[7];
    const float* b3 = (const float*)d_in[8];
    const float* Ws = (const float*)d_in[9];
    const float* bs = (const float*)d_in[10];

    float* out      = (float*)d_out;
    float* out_newx = out;
    float* out_adj  = out + (size_t)CC * FF;
    float* out_S    = out + (size_t)CC * FF + (size_t)CC * CC + CC;

    float *pP, *ph, *ph3;
    cudaGetSymbolAddress((void**)&pP,  g_P);
    cudaGetSymbolAddress((void**)&ph,  g_h);
    cudaGetSymbolAddress((void**)&ph3, g_h3);

    cudaFuncSetAttribute(k_gemm_tc, cudaFuncAttributeMaxDynamicSharedMemorySize,
                         GEMM_SMEM_BYTES);

    const int TB = 256;
    int gN = (NN + TB - 1) / TB;
    int gE = (EE + TB - 1) / TB;
    int gW = (NN * 32 + TB - 1) / TB;  // warp-per-node kernels
    int gP = (NN + 7) / 8;             // 8 warps/block, warp-per-node prop
    int nbScan = (NN + 1023) / 1024;

    // graph build (CSR) + degree normalization
    k_init<<<gN, TB>>>();
    k_count<<<gE, TB>>>(dst);
    k_scan1<<<nbScan, 1024>>>();
    k_scan2<<<1, 32>>>(nbScan);
    k_scan3<<<gN, TB>>>();
    k_scatter<<<gE, TB>>>(src, dst);

    // 3-layer GCN (propagate in input space, then tensor-core linear+bias+relu)
    dim3 gemmGrid1(HH / GBN, (NN + GBM - 1) / GBM);
    dim3 gemmGrid3(CC / GBN, (NN + GBM - 1) / GBM);
    k_prop<FF><<<gP, TB>>>(x, pP);
    k_gemm_tc<<<gemmGrid1, 512, GEMM_SMEM_BYTES>>>(pP, W1, b1, ph, NN, HH, FF, 1);
    k_prop<HH><<<gP, TB>>>(ph, pP);
    k_gemm_tc<<<gemmGrid1, 512, GEMM_SMEM_BYTES>>>(pP, W2, b2, ph, NN, HH, HH, 1);
    k_prop<HH><<<gP, TB>>>(ph, pP);
    k_gemm_tc<<<gemmGrid3, 512, GEMM_SMEM_BYTES>>>(pP, W3, b3, ph3, NN, CC, HH, 0);

    // softmax(relu) -> S output + hard clusters
    k_softmax<<<NN, 512>>>(ph3, out_S);

    // score layer on intra-cluster subgraph
    k_hs<<<gW, TB>>>(x, Ws);
    k_intra<<<gW, TB>>>();
    k_score<<<gW, TB>>>(bs);
    k_segmax<<<gN, TB>>>();
    k_argidx<<<gN, TB>>>();

    // pooled outputs: new_x, new_adj, new_batch (batch is all zeros)
    k_newx<<<CC, FF>>>(x, out_newx);
    int zn = CC * CC + CC;  // adjacency + new_batch region
    k_zero<<<(zn + TB - 1) / TB, TB>>>(out_adj, zn);
    k_adj<<<gE, TB>>>(src, dst, out_adj);
}

// round 8
// speedup vs baseline: 2.5376x; 1.1903x over previous
#include <cuda_runtime.h>
#include <cuda_fp16.h>
#include <math.h>
#include <stdint.h>

#define NN 50000
#define FF 128
#define HH 256
#define CC 512
#define EE 800000

// ---------------- scratch (device globals; no allocation allowed) -------------
__device__ int      g_cnt[NN];
__device__ int      g_rowstart[NN];
__device__ int      g_fill[NN];
__device__ int      g_incl[NN];
__device__ int      g_bsum[64];
__device__ int      g_csr[EE];
__device__ float    g_inv[NN];
__device__ float    g_hs[NN];
__device__ float    g_invs[NN];
__device__ float    g_score[NN];
__device__ int      g_cluster[NN];
__device__ unsigned g_cmaxkey[CC];
__device__ int      g_idx[CC];
__device__ int      g_nonempty[CC];
__device__ float    g_P[(size_t)NN * HH];   // propagation output (<=256 feats)
__device__ float    g_h[(size_t)NN * HH];   // hidden activations
__device__ float    g_h3[(size_t)NN * CC];  // layer-3 pre-softmax
__device__ float    g_Wt[(size_t)CC * HH];  // transposed weights [N,K], max 512x256

// monotonic float<->uint key for atomicMax on floats
__device__ __forceinline__ unsigned fkey(float f) {
    unsigned u = __float_as_uint(f);
    return (u & 0x80000000u) ? ~u : (u | 0x80000000u);
}
__device__ __forceinline__ float fdec(unsigned k) {
    return (k & 0x80000000u) ? __uint_as_float(k ^ 0x80000000u)
                             : __uint_as_float(~k);
}

// ---------------- setup kernels ----------------------------------------------
__global__ void k_init() {
    int i = blockIdx.x * blockDim.x + threadIdx.x;
    if (i < NN) g_cnt[i] = 0;
    if (i < CC) { g_cmaxkey[i] = 0u; g_idx[i] = 0x7FFFFFFF; g_nonempty[i] = 0; }
}

__global__ void k_count(const int* __restrict__ dst) {
    int e = blockIdx.x * blockDim.x + threadIdx.x;
    if (e < EE) atomicAdd(&g_cnt[dst[e]], 1);
}

__global__ void k_scan1() {  // per-1024 block inclusive scan of g_cnt -> g_incl
    __shared__ int s[1024];
    int g = blockIdx.x * 1024 + threadIdx.x;
    int v = (g < NN) ? g_cnt[g] : 0;
    s[threadIdx.x] = v;
    __syncthreads();
    for (int off = 1; off < 1024; off <<= 1) {
        int t = (threadIdx.x >= off) ? s[threadIdx.x - off] : 0;
        __syncthreads();
        s[threadIdx.x] += t;
        __syncthreads();
    }
    if (g < NN) g_incl[g] = s[threadIdx.x];
    if (threadIdx.x == 1023) g_bsum[blockIdx.x] = s[1023];
}

__global__ void k_scan2(int nb) {
    if (threadIdx.x == 0 && blockIdx.x == 0) {
        int a = 0;
        for (int i = 0; i < nb; i++) { int t = g_bsum[i]; g_bsum[i] = a; a += t; }
    }
}

__global__ void k_scan3() {
    int g = blockIdx.x * blockDim.x + threadIdx.x;
    if (g < NN) {
        int rs = g_incl[g] + g_bsum[g >> 10] - g_cnt[g];
        g_rowstart[g] = rs;
        g_fill[g] = rs;
        g_inv[g] = rsqrtf((float)g_cnt[g] + 1.0f);
    }
}

__global__ void k_scatter(const int* __restrict__ src, const int* __restrict__ dst) {
    int e = blockIdx.x * blockDim.x + threadIdx.x;
    if (e < EE) {
        int p = atomicAdd(&g_fill[dst[e]], 1);
        g_csr[p] = src[e];
    }
}

// ------- GCN propagation, warp-per-node, float4 --------------------------------
template <int F>
__global__ __launch_bounds__(256) void k_prop(const float* __restrict__ X,
                                              float* __restrict__ Y) {
    constexpr int V = F / 128;
    int w = blockIdx.x * (blockDim.x >> 5) + (threadIdx.x >> 5);
    int lane = threadIdx.x & 31;
    if (w >= NN) return;
    float invi = g_inv[w];
    const float4* Xw = (const float4*)(X + (size_t)w * F);
    float4 acc[V];
#pragma unroll
    for (int v = 0; v < V; v++) {
        float4 t = Xw[lane + v * 32];
        acc[v] = make_float4(invi * t.x, invi * t.y, invi * t.z, invi * t.w);
    }
    int beg = g_rowstart[w];
    int end = beg + g_cnt[w];
    int j = beg;
    for (; j + 4 <= end; j += 4) {
        int s0 = g_csr[j], s1 = g_csr[j + 1], s2 = g_csr[j + 2], s3 = g_csr[j + 3];
        float w0 = g_inv[s0], w1 = g_inv[s1], w2 = g_inv[s2], w3 = g_inv[s3];
        const float4* r0 = (const float4*)(X + (size_t)s0 * F);
        const float4* r1 = (const float4*)(X + (size_t)s1 * F);
        const float4* r2 = (const float4*)(X + (size_t)s2 * F);
        const float4* r3 = (const float4*)(X + (size_t)s3 * F);
#pragma unroll
        for (int v = 0; v < V; v++) {
            float4 t0 = r0[lane + v * 32];
            float4 t1 = r1[lane + v * 32];
            float4 t2 = r2[lane + v * 32];
            float4 t3 = r3[lane + v * 32];
            acc[v].x += w0 * t0.x + w1 * t1.x + w2 * t2.x + w3 * t3.x;
            acc[v].y += w0 * t0.y + w1 * t1.y + w2 * t2.y + w3 * t3.y;
            acc[v].z += w0 * t0.z + w1 * t1.z + w2 * t2.z + w3 * t3.z;
            acc[v].w += w0 * t0.w + w1 * t1.w + w2 * t2.w + w3 * t3.w;
        }
    }
    for (; j < end; j++) {
        int s0 = g_csr[j];
        float w0 = g_inv[s0];
        const float4* r0 = (const float4*)(X + (size_t)s0 * F);
#pragma unroll
        for (int v = 0; v < V; v++) {
            float4 t0 = r0[lane + v * 32];
            acc[v].x += w0 * t0.x; acc[v].y += w0 * t0.y;
            acc[v].z += w0 * t0.z; acc[v].w += w0 * t0.w;
        }
    }
    float4* Yw = (float4*)(Y + (size_t)w * F);
#pragma unroll
    for (int v = 0; v < V; v++) {
        Yw[lane + v * 32] = make_float4(invi * acc[v].x, invi * acc[v].y,
                                        invi * acc[v].z, invi * acc[v].w);
    }
}

// ---------------- weight transpose W[K,N] -> Wt[N,K] ---------------------------
__global__ void k_transW(const float* __restrict__ W, float* __restrict__ Wt,
                         int K, int N) {
    __shared__ float tile[32][33];
    int n0 = blockIdx.x * 32, k0 = blockIdx.y * 32;
    int tx = threadIdx.x, ty = threadIdx.y;  // 32 x 8
#pragma unroll
    for (int i = 0; i < 4; i++)
        tile[ty + i * 8][tx] = W[(size_t)(k0 + ty + i * 8) * N + n0 + tx];
    __syncthreads();
#pragma unroll
    for (int i = 0; i < 4; i++)
        Wt[(size_t)(n0 + ty + i * 8) * K + k0 + tx] = tile[tx][ty + i * 8];
}

// ---------------- fp16x3 tensor-core GEMM --------------------------------------
// C[M,N] = A[M,K] @ Bt[N,K]^T + bias, optional relu.
// a = ah + al (fp16 split, |al| <= 2^-11|a|); products exact in fp32 accum;
// 3 passes (ah*bh + ah*bl + al*bh) drop only al*bl <= 2^-22 -> fp32-class.
// Block tile 128x128x32, 512 threads = 16 warps (4x4), warp tile 32x32.
// m16n8k16.f16 runs at 2x the tf32 MMA rate.
#define GBM 128
#define GBN 128
#define GBK 32
#define HSTR 40                     // halves per smem row (32 + 8 pad)
#define HTILE (128 * HSTR)          // halves per tile (A or B, hi or lo)
#define BUFH (4 * HTILE)            // Ah, Al, Bh, Bl
#define GEMM_SMEM_BYTES (2 * BUFH * 2)   // double buffer, 2B/half = 81920

__device__ __forceinline__ void f16_split(float v, __half& hi, __half& lo) {
    hi = __float2half_rn(v);
    lo = __float2half_rn(v - __half2float(hi));
}

__device__ __forceinline__ void mma_f16(float c[4], uint32_t a0, uint32_t a1,
                                        uint32_t a2, uint32_t a3,
                                        uint32_t b0, uint32_t b1) {
    asm volatile(
        "mma.sync.aligned.m16n8k16.row.col.f32.f16.f16.f32 "
        "{%0,%1,%2,%3}, {%4,%5,%6,%7}, {%8,%9}, {%0,%1,%2,%3};"
        : "+f"(c[0]), "+f"(c[1]), "+f"(c[2]), "+f"(c[3])
        : "r"(a0), "r"(a1), "r"(a2), "r"(a3), "r"(b0), "r"(b1));
}

__global__ __launch_bounds__(512, 1) void k_gemm_fp16(
    const float* __restrict__ A, const float* __restrict__ Bt,
    const float* __restrict__ bias, float* __restrict__ C,
    int M, int N, int K, int doRelu) {
    extern __shared__ __half hsm[];

    int tid = threadIdx.x;
    int warp = tid >> 5;
    int lane = tid & 31;
    int gid = lane >> 2;   // groupID 0..7
    int tig = lane & 3;    // thread-in-group 0..3
    int wm = warp >> 2;    // 0..3
    int wn = warp & 3;     // 0..3

    int m0 = blockIdx.y * GBM;
    int n0 = blockIdx.x * GBN;

    float acc[2][4][4];
#pragma unroll
    for (int mt = 0; mt < 2; mt++)
#pragma unroll
        for (int nt = 0; nt < 4; nt++)
#pragma unroll
            for (int r = 0; r < 4; r++) acc[mt][nt][r] = 0.0f;

    // global load indexing: 128 rows x 32 cols per tile, 2 passes of 64 rows
    int g_r = tid >> 3;           // 0..63
    int g_c = (tid & 7) * 4;      // col (k) within tile

    float4 arv[2], brv[2];

    auto loadG = [&](int t) {
        int k0 = t * GBK;
#pragma unroll
        for (int p = 0; p < 2; p++) {
            int m = m0 + g_r + p * 64;
            arv[p] = make_float4(0.f, 0.f, 0.f, 0.f);
            if (m < M) arv[p] = *(const float4*)&A[(size_t)m * K + k0 + g_c];
            brv[p] = *(const float4*)&Bt[(size_t)(n0 + g_r + p * 64) * K + k0 + g_c];
        }
    };

    auto storeSplit = [&](int buf) {
        __half* Ah = hsm + buf * BUFH;
        __half* Al = Ah + HTILE;
        __half* Bh = Al + HTILE;
        __half* Bl = Bh + HTILE;
#pragma unroll
        for (int p = 0; p < 2; p++) {
            int row = g_r + p * 64;
            __half h0, l0, h1, l1, h2, l2, h3, l3;
            f16_split(arv[p].x, h0, l0); f16_split(arv[p].y, h1, l1);
            f16_split(arv[p].z, h2, l2); f16_split(arv[p].w, h3, l3);
            __half2* pa = (__half2*)&Ah[row * HSTR + g_c];
            pa[0] = __halves2half2(h0, h1); pa[1] = __halves2half2(h2, h3);
            __half2* pal = (__half2*)&Al[row * HSTR + g_c];
            pal[0] = __halves2half2(l0, l1); pal[1] = __halves2half2(l2, l3);
            f16_split(brv[p].x, h0, l0); f16_split(brv[p].y, h1, l1);
            f16_split(brv[p].z, h2, l2); f16_split(brv[p].w, h3, l3);
            __half2* pb = (__half2*)&Bh[row * HSTR + g_c];
            pb[0] = __halves2half2(h0, h1); pb[1] = __halves2half2(h2, h3);
            __half2* pbl = (__half2*)&Bl[row * HSTR + g_c];
            pbl[0] = __halves2half2(l0, l1); pbl[1] = __halves2half2(l2, l3);
        }
    };

    auto compute = [&](int buf) {
        const __half* Ah = hsm + buf * BUFH;
        const __half* Al = Ah + HTILE;
        const __half* Bh = Al + HTILE;
        const __half* Bl = Bh + HTILE;
#pragma unroll
        for (int ks = 0; ks < GBK / 16; ks++) {
            int kc = ks * 16 + 2 * tig;
            uint32_t ah[2][4], al[2][4];
#pragma unroll
            for (int mt = 0; mt < 2; mt++) {
                int rm = wm * 32 + mt * 16;
                ah[mt][0] = *(const uint32_t*)&Ah[(rm + gid) * HSTR + kc];
                ah[mt][1] = *(const uint32_t*)&Ah[(rm + gid + 8) * HSTR + kc];
                ah[mt][2] = *(const uint32_t*)&Ah[(rm + gid) * HSTR + kc + 8];
                ah[mt][3] = *(const uint32_t*)&Ah[(rm + gid + 8) * HSTR + kc + 8];
                al[mt][0] = *(const uint32_t*)&Al[(rm + gid) * HSTR + kc];
                al[mt][1] = *(const uint32_t*)&Al[(rm + gid + 8) * HSTR + kc];
                al[mt][2] = *(const uint32_t*)&Al[(rm + gid) * HSTR + kc + 8];
                al[mt][3] = *(const uint32_t*)&Al[(rm + gid + 8) * HSTR + kc + 8];
            }
            uint32_t bh[4][2], bl[4][2];
#pragma unroll
            for (int nt = 0; nt < 4; nt++) {
                int cn = wn * 32 + nt * 8 + gid;
                bh[nt][0] = *(const uint32_t*)&Bh[cn * HSTR + kc];
                bh[nt][1] = *(const uint32_t*)&Bh[cn * HSTR + kc + 8];
                bl[nt][0] = *(const uint32_t*)&Bl[cn * HSTR + kc];
                bl[nt][1] = *(const uint32_t*)&Bl[cn * HSTR + kc + 8];
            }
#pragma unroll
            for (int mt = 0; mt < 2; mt++)
#pragma unroll
                for (int nt = 0; nt < 4; nt++) {
                    mma_f16(acc[mt][nt], ah[mt][0], ah[mt][1], ah[mt][2], ah[mt][3],
                            bl[nt][0], bl[nt][1]);
                    mma_f16(acc[mt][nt], al[mt][0], al[mt][1], al[mt][2], al[mt][3],
                            bh[nt][0], bh[nt][1]);
                    mma_f16(acc[mt][nt], ah[mt][0], ah[mt][1], ah[mt][2], ah[mt][3],
                            bh[nt][0], bh[nt][1]);
                }
        }
    };

    int T = K / GBK;
    loadG(0);
    storeSplit(0);
    __syncthreads();
    for (int t = 0; t < T; t++) {
        int buf = t & 1;
        bool more = (t + 1 < T);
        if (more) loadG(t + 1);
        compute(buf);
        if (more) storeSplit(buf ^ 1);
        __syncthreads();
    }

    // epilogue: bias (+relu), guarded stores
#pragma unroll
    for (int mt = 0; mt < 2; mt++) {
        int rbase = m0 + wm * 32 + mt * 16 + gid;
#pragma unroll
        for (int nt = 0; nt < 4; nt++) {
            int c0 = n0 + wn * 32 + nt * 8 + tig * 2;
            float bia0 = bias[c0], bia1 = bias[c0 + 1];
#pragma unroll
            for (int half = 0; half < 2; half++) {
                int m = rbase + half * 8;
                if (m >= M) continue;
                float v0 = acc[mt][nt][half * 2 + 0] + bia0;
                float v1 = acc[mt][nt][half * 2 + 1] + bia1;
                if (doRelu) { v0 = fmaxf(v0, 0.f); v1 = fmaxf(v1, 0.f); }
                C[(size_t)m * N + c0] = v0;
                C[(size_t)m * N + c0 + 1] = v1;
            }
        }
    }
}

// ---------------- softmax(relu(h3)) row-wise + argmax -------------------------
__global__ __launch_bounds__(512) void k_softmax(const float* __restrict__ H,
                                                 float* __restrict__ S) {
    __shared__ float sv[512];
    __shared__ int si[512];
    int i = blockIdx.x, c = threadIdx.x;
    float z = fmaxf(H[(size_t)i * CC + c], 0.0f);
    sv[c] = z; si[c] = c;
    __syncthreads();
    for (int off = 256; off > 0; off >>= 1) {
        if (c < off) {
            float v2 = sv[c + off]; int i2 = si[c + off];
            if (v2 > sv[c] || (v2 == sv[c] && i2 < si[c])) { sv[c] = v2; si[c] = i2; }
        }
        __syncthreads();
    }
    float m = sv[0]; int am = si[0];
    __syncthreads();
    float e = expf(z - m);
    sv[c] = e;
    __syncthreads();
    for (int off = 256; off > 0; off >>= 1) {
        if (c < off) sv[c] += sv[c + off];
        __syncthreads();
    }
    float invsum = 1.0f / sv[0];
    S[(size_t)i * CC + c] = e * invsum;
    if (c == 0) g_cluster[i] = am;
}

// ---------------- score layer ------------------------------------------------
__global__ void k_hs(const float* __restrict__ x, const float* __restrict__ Ws) {
    int t = blockIdx.x * blockDim.x + threadIdx.x;
    int w = t >> 5, lane = t & 31;
    if (w >= NN) return;
    float a = 0.0f;
#pragma unroll
    for (int r = 0; r < 4; r++) {
        int f = lane + 32 * r;
        a += x[(size_t)w * FF + f] * Ws[f];
    }
#pragma unroll
    for (int off = 16; off > 0; off >>= 1) a += __shfl_down_sync(0xFFFFFFFFu, a, off);
    if (lane == 0) g_hs[w] = a;
}

__global__ void k_intra() {
    int t = blockIdx.x * blockDim.x + threadIdx.x;
    int i = t >> 5, lane = t & 31;
    if (i >= NN) return;
    int myc = g_cluster[i];
    int beg = g_rowstart[i], end = beg + g_cnt[i];
    int cint = 0;
    for (int j = beg + lane; j < end; j += 32)
        cint += (g_cluster[g_csr[j]] == myc) ? 1 : 0;
#pragma unroll
    for (int off = 16; off > 0; off >>= 1) cint += __shfl_down_sync(0xFFFFFFFFu, cint, off);
    if (lane == 0) {
        g_invs[i] = rsqrtf((float)cint + 1.0f);
        if (cint > 0) atomicOr(&g_nonempty[myc], 1);
    }
}

__global__ void k_score(const float* __restrict__ bs) {
    int t = blockIdx.x * blockDim.x + threadIdx.x;
    int i = t >> 5, lane = t & 31;
    if (i >= NN) return;
    int myc = g_cluster[i];
    int beg = g_rowstart[i], end = beg + g_cnt[i];
    float acc = 0.0f;
    for (int j = beg + lane; j < end; j += 32) {
        int s = g_csr[j];
        if (g_cluster[s] == myc) acc += g_invs[s] * g_hs[s];
    }
#pragma unroll
    for (int off = 16; off > 0; off >>= 1) acc += __shfl_down_sync(0xFFFFFFFFu, acc, off);
    if (lane == 0) {
        float invi = g_invs[i];
        float agg = invi * (acc + invi * g_hs[i]);
        g_score[i] = tanhf(agg + bs[0]);
    }
}

__global__ void k_segmax() {
    int i = blockIdx.x * blockDim.x + threadIdx.x;
    if (i < NN) atomicMax(&g_cmaxkey[g_cluster[i]], fkey(g_score[i]));
}

__global__ void k_argidx() {
    int i = blockIdx.x * blockDim.x + threadIdx.x;
    if (i < NN && fkey(g_score[i]) >= g_cmaxkey[g_cluster[i]])
        atomicMin(&g_idx[g_cluster[i]], i);
}

// ---------------- outputs ----------------------------------------------------
__global__ void k_newx(const float* __restrict__ x, float* __restrict__ out) {
    int c = blockIdx.x, f = threadIdx.x;
    float v = 0.0f;
    if (g_nonempty[c]) {
        float alpha = fdec(g_cmaxkey[c]);
        int id = g_idx[c];
        v = x[(size_t)id * FF + f] * alpha;
    }
    out[(size_t)c * FF + f] = v;
}

__global__ void k_zero(float* __restrict__ p, int n) {
    int i = blockIdx.x * blockDim.x + threadIdx.x;
    if (i < n) p[i] = 0.0f;
}

__global__ void k_adj(const int* __restrict__ src, const int* __restrict__ dst,
                      float* __restrict__ adj) {
    int e = blockIdx.x * blockDim.x + threadIdx.x;
    if (e >= EE) return;
    int ci = g_cluster[src[e]], cj = g_cluster[dst[e]];
    if (ci != cj && g_nonempty[ci] && g_nonempty[cj]) adj[ci * CC + cj] = 1.0f;
}

// ---------------- host -------------------------------------------------------
extern "C" void kernel_launch(void* const* d_in, const int* in_sizes, int n_in,
                              void* d_out, int out_size) {
    const float* x  = (const float*)d_in[0];
    const int*   ei = (const int*)d_in[1];
    const int*   src = ei;
    const int*   dst = ei + EE;
    const float* W1 = (const float*)d_in[3];
    const float* b1 = (const float*)d_in[4];
    const float* W2 = (const float*)d_in[5];
    const float* b2 = (const float*)d_in[6];
    const float* W3 = (const float*)d_in[7];
    const float* b3 = (const float*)d_in[8];
    const float* Ws = (const float*)d_in[9];
    const float* bs = (const float*)d_in[10];

    float* out      = (float*)d_out;
    float* out_newx = out;
    float* out_adj  = out + (size_t)CC * FF;
    float* out_S    = out + (size_t)CC * FF + (size_t)CC * CC + CC;

    float *pP, *ph, *ph3, *pWt;
    cudaGetSymbolAddress((void**)&pP,  g_P);
    cudaGetSymbolAddress((void**)&ph,  g_h);
    cudaGetSymbolAddress((void**)&ph3, g_h3);
    cudaGetSymbolAddress((void**)&pWt, g_Wt);

    cudaFuncSetAttribute(k_gemm_fp16, cudaFuncAttributeMaxDynamicSharedMemorySize,
                         GEMM_SMEM_BYTES);

    const int TB = 256;
    int gN = (NN + TB - 1) / TB;
    int gE = (EE + TB - 1) / TB;
    int gW = (NN * 32 + TB - 1) / TB;
    int gP = (NN + 7) / 8;
    int nbScan = (NN + 1023) / 1024;
    int gM = (NN + GBM - 1) / GBM;

    // graph build (CSR) + degree normalization
    k_init<<<gN, TB>>>();
    k_count<<<gE, TB>>>(dst);
    k_scan1<<<nbScan, 1024>>>();
    k_scan2<<<1, 32>>>(nbScan);
    k_scan3<<<gN, TB>>>();
    k_scatter<<<gE, TB>>>(src, dst);

    // 3-layer GCN: propagate (input space) -> fp16x3 tensor-core linear
    dim3 tb(32, 8);
    k_prop<FF><<<gP, TB>>>(x, pP);
    k_transW<<<dim3(HH / 32, FF / 32), tb>>>(W1, pWt, FF, HH);
    k_gemm_fp16<<<dim3(HH / GBN, gM), 512, GEMM_SMEM_BYTES>>>(pP, pWt, b1, ph, NN, HH, FF, 1);
    k_prop<HH><<<gP, TB>>>(ph, pP);
    k_transW<<<dim3(HH / 32, HH / 32), tb>>>(W2, pWt, HH, HH);
    k_gemm_fp16<<<dim3(HH / GBN, gM), 512, GEMM_SMEM_BYTES>>>(pP, pWt, b2, ph, NN, HH, HH, 1);
    k_prop<HH><<<gP, TB>>>(ph, pP);
    k_transW<<<dim3(CC / 32, HH / 32), tb>>>(W3, pWt, HH, CC);
    k_gemm_fp16<<<dim3(CC / GBN, gM), 512, GEMM_SMEM_BYTES>>>(pP, pWt, b3, ph3, NN, CC, HH, 0);

    // softmax(relu) -> S output + hard clusters
    k_softmax<<<NN, 512>>>(ph3, out_S);

    // score layer on intra-cluster subgraph
    k_hs<<<gW, TB>>>(x, Ws);
    k_intra<<<gW, TB>>>();
    k_score<<<gW, TB>>>(bs);
    k_segmax<<<gN, TB>>>();
    k_argidx<<<gN, TB>>>();

    // pooled outputs
    k_newx<<<CC, FF>>>(x, out_newx);
    int zn = CC * CC + CC;
    k_zero<<<(zn + TB - 1) / TB, TB>>>(out_adj, zn);
    k_adj<<<gE, TB>>>(src, dst, out_adj);
}

// round 11
// speedup vs baseline: 3.4201x; 1.3478x over previous
#include <cuda_runtime.h>
#include <cuda_fp16.h>
#include <math.h>
#include <stdint.h>

#define NN 50000
#define FF 128
#define HH 256
#define CC 512
#define EE 800000

// ---------------- scratch (device globals; no allocation allowed) -------------
__device__ int      g_cnt[NN];
__device__ int      g_rowstart[NN];
__device__ int      g_fill[NN];
__device__ int      g_incl[NN];
__device__ int      g_bsum[64];
__device__ int      g_csr[EE];
__device__ float    g_inv[NN];
__device__ float    g_hs[NN];
__device__ float    g_invs[NN];
__device__ float    g_ivh[NN];      // invs * hs (score-layer gather array)
__device__ float    g_score[NN];
__device__ int      g_cluster[NN];
__device__ unsigned long long g_ckey[CC];  // (fkey(score)<<32)|(0x7FFFFFFF-i)
__device__ int      g_nonempty[CC];
__device__ float    g_P[(size_t)NN * HH];   // propagation output (<=256 feats)
__device__ float    g_h[(size_t)NN * HH];   // hidden activations
__device__ float    g_h3[(size_t)NN * CC];  // layer-3 pre-softmax
__device__ float    g_Wt[(size_t)CC * HH];  // transposed weights [N,K], max 512x256

// monotonic float<->uint key for atomicMax on floats
__device__ __forceinline__ unsigned fkey(float f) {
    unsigned u = __float_as_uint(f);
    return (u & 0x80000000u) ? ~u : (u | 0x80000000u);
}
__device__ __forceinline__ float fdec(unsigned k) {
    return (k & 0x80000000u) ? __uint_as_float(k ^ 0x80000000u)
                             : __uint_as_float(~k);
}

// ---------------- setup kernels ----------------------------------------------
__global__ void k_init() {
    int i = blockIdx.x * blockDim.x + threadIdx.x;
    if (i < NN) g_cnt[i] = 0;
    if (i < CC) { g_ckey[i] = 0ull; g_nonempty[i] = 0; }
}

__global__ void k_count(const int* __restrict__ dst) {
    int e = blockIdx.x * blockDim.x + threadIdx.x;
    if (e < EE) atomicAdd(&g_cnt[dst[e]], 1);
}

__global__ void k_scan1() {  // per-1024 block inclusive scan of g_cnt -> g_incl
    __shared__ int s[1024];
    int g = blockIdx.x * 1024 + threadIdx.x;
    int v = (g < NN) ? g_cnt[g] : 0;
    s[threadIdx.x] = v;
    __syncthreads();
    for (int off = 1; off < 1024; off <<= 1) {
        int t = (threadIdx.x >= off) ? s[threadIdx.x - off] : 0;
        __syncthreads();
        s[threadIdx.x] += t;
        __syncthreads();
    }
    if (g < NN) g_incl[g] = s[threadIdx.x];
    if (threadIdx.x == 1023) g_bsum[blockIdx.x] = s[1023];
}

__global__ void k_scan2(int nb) {
    if (threadIdx.x == 0 && blockIdx.x == 0) {
        int a = 0;
        for (int i = 0; i < nb; i++) { int t = g_bsum[i]; g_bsum[i] = a; a += t; }
    }
}

__global__ void k_scan3() {
    int g = blockIdx.x * blockDim.x + threadIdx.x;
    if (g < NN) {
        int rs = g_incl[g] + g_bsum[g >> 10] - g_cnt[g];
        g_rowstart[g] = rs;
        g_fill[g] = rs;
        g_inv[g] = rsqrtf((float)g_cnt[g] + 1.0f);
    }
}

__global__ void k_scatter(const int* __restrict__ src, const int* __restrict__ dst) {
    int e = blockIdx.x * blockDim.x + threadIdx.x;
    if (e < EE) {
        int p = atomicAdd(&g_fill[dst[e]], 1);
        g_csr[p] = src[e];
    }
}

// ------- GCN propagation, warp-per-node, float4 --------------------------------
template <int F>
__global__ __launch_bounds__(256) void k_prop(const float* __restrict__ X,
                                              float* __restrict__ Y) {
    constexpr int V = F / 128;
    int w = blockIdx.x * (blockDim.x >> 5) + (threadIdx.x >> 5);
    int lane = threadIdx.x & 31;
    if (w >= NN) return;
    float invi = g_inv[w];
    const float4* Xw = (const float4*)(X + (size_t)w * F);
    float4 acc[V];
#pragma unroll
    for (int v = 0; v < V; v++) {
        float4 t = Xw[lane + v * 32];
        acc[v] = make_float4(invi * t.x, invi * t.y, invi * t.z, invi * t.w);
    }
    int beg = g_rowstart[w];
    int end = beg + g_cnt[w];
    int j = beg;
    for (; j + 4 <= end; j += 4) {
        int s0 = g_csr[j], s1 = g_csr[j + 1], s2 = g_csr[j + 2], s3 = g_csr[j + 3];
        float w0 = g_inv[s0], w1 = g_inv[s1], w2 = g_inv[s2], w3 = g_inv[s3];
        const float4* r0 = (const float4*)(X + (size_t)s0 * F);
        const float4* r1 = (const float4*)(X + (size_t)s1 * F);
        const float4* r2 = (const float4*)(X + (size_t)s2 * F);
        const float4* r3 = (const float4*)(X + (size_t)s3 * F);
#pragma unroll
        for (int v = 0; v < V; v++) {
            float4 t0 = r0[lane + v * 32];
            float4 t1 = r1[lane + v * 32];
            float4 t2 = r2[lane + v * 32];
            float4 t3 = r3[lane + v * 32];
            acc[v].x += w0 * t0.x + w1 * t1.x + w2 * t2.x + w3 * t3.x;
            acc[v].y += w0 * t0.y + w1 * t1.y + w2 * t2.y + w3 * t3.y;
            acc[v].z += w0 * t0.z + w1 * t1.z + w2 * t2.z + w3 * t3.z;
            acc[v].w += w0 * t0.w + w1 * t1.w + w2 * t2.w + w3 * t3.w;
        }
    }
    for (; j < end; j++) {
        int s0 = g_csr[j];
        float w0 = g_inv[s0];
        const float4* r0 = (const float4*)(X + (size_t)s0 * F);
#pragma unroll
        for (int v = 0; v < V; v++) {
            float4 t0 = r0[lane + v * 32];
            acc[v].x += w0 * t0.x; acc[v].y += w0 * t0.y;
            acc[v].z += w0 * t0.z; acc[v].w += w0 * t0.w;
        }
    }
    float4* Yw = (float4*)(Y + (size_t)w * F);
#pragma unroll
    for (int v = 0; v < V; v++) {
        Yw[lane + v * 32] = make_float4(invi * acc[v].x, invi * acc[v].y,
                                        invi * acc[v].z, invi * acc[v].w);
    }
}

// ---------------- weight transpose W[K,N] -> Wt[N,K] ---------------------------
__global__ void k_transW(const float* __restrict__ W, float* __restrict__ Wt,
                         int K, int N) {
    __shared__ float tile[32][33];
    int n0 = blockIdx.x * 32, k0 = blockIdx.y * 32;
    int tx = threadIdx.x, ty = threadIdx.y;  // 32 x 8
#pragma unroll
    for (int i = 0; i < 4; i++)
        tile[ty + i * 8][tx] = W[(size_t)(k0 + ty + i * 8) * N + n0 + tx];
    __syncthreads();
#pragma unroll
    for (int i = 0; i < 4; i++)
        Wt[(size_t)(n0 + ty + i * 8) * K + k0 + tx] = tile[tx][ty + i * 8];
}

// ---------------- fp16x3 tensor-core GEMM --------------------------------------
// C[M,N] = A[M,K] @ Bt[N,K]^T + bias, optional relu.
// a = ah + al (fp16 split); 3 passes drop only al*bl <= 2^-22 -> fp32-class.
#define GBM 128
#define GBN 128
#define GBK 32
#define HSTR 40                     // halves per smem row (32 + 8 pad)
#define HTILE (128 * HSTR)
#define BUFH (4 * HTILE)            // Ah, Al, Bh, Bl
#define GEMM_SMEM_BYTES (2 * BUFH * 2)   // 81920

__device__ __forceinline__ void f16_split(float v, __half& hi, __half& lo) {
    hi = __float2half_rn(v);
    lo = __float2half_rn(v - __half2float(hi));
}

__device__ __forceinline__ void mma_f16(float c[4], uint32_t a0, uint32_t a1,
                                        uint32_t a2, uint32_t a3,
                                        uint32_t b0, uint32_t b1) {
    asm volatile(
        "mma.sync.aligned.m16n8k16.row.col.f32.f16.f16.f32 "
        "{%0,%1,%2,%3}, {%4,%5,%6,%7}, {%8,%9}, {%0,%1,%2,%3};"
        : "+f"(c[0]), "+f"(c[1]), "+f"(c[2]), "+f"(c[3])
        : "r"(a0), "r"(a1), "r"(a2), "r"(a3), "r"(b0), "r"(b1));
}

__global__ __launch_bounds__(512, 1) void k_gemm_fp16(
    const float* __restrict__ A, const float* __restrict__ Bt,
    const float* __restrict__ bias, float* __restrict__ C,
    int M, int N, int K, int doRelu) {
    extern __shared__ __half hsm[];

    int tid = threadIdx.x;
    int warp = tid >> 5;
    int lane = tid & 31;
    int gid = lane >> 2;
    int tig = lane & 3;
    int wm = warp >> 2;
    int wn = warp & 3;

    int m0 = blockIdx.y * GBM;
    int n0 = blockIdx.x * GBN;

    float acc[2][4][4];
#pragma unroll
    for (int mt = 0; mt < 2; mt++)
#pragma unroll
        for (int nt = 0; nt < 4; nt++)
#pragma unroll
            for (int r = 0; r < 4; r++) acc[mt][nt][r] = 0.0f;

    int g_r = tid >> 3;
    int g_c = (tid & 7) * 4;

    float4 arv[2], brv[2];

    auto loadG = [&](int t) {
        int k0 = t * GBK;
#pragma unroll
        for (int p = 0; p < 2; p++) {
            int m = m0 + g_r + p * 64;
            arv[p] = make_float4(0.f, 0.f, 0.f, 0.f);
            if (m < M) arv[p] = *(const float4*)&A[(size_t)m * K + k0 + g_c];
            brv[p] = *(const float4*)&Bt[(size_t)(n0 + g_r + p * 64) * K + k0 + g_c];
        }
    };

    auto storeSplit = [&](int buf) {
        __half* Ah = hsm + buf * BUFH;
        __half* Al = Ah + HTILE;
        __half* Bh = Al + HTILE;
        __half* Bl = Bh + HTILE;
#pragma unroll
        for (int p = 0; p < 2; p++) {
            int row = g_r + p * 64;
            __half h0, l0, h1, l1, h2, l2, h3, l3;
            f16_split(arv[p].x, h0, l0); f16_split(arv[p].y, h1, l1);
            f16_split(arv[p].z, h2, l2); f16_split(arv[p].w, h3, l3);
            __half2* pa = (__half2*)&Ah[row * HSTR + g_c];
            pa[0] = __halves2half2(h0, h1); pa[1] = __halves2half2(h2, h3);
            __half2* pal = (__half2*)&Al[row * HSTR + g_c];
            pal[0] = __halves2half2(l0, l1); pal[1] = __halves2half2(l2, l3);
            f16_split(brv[p].x, h0, l0); f16_split(brv[p].y, h1, l1);
            f16_split(brv[p].z, h2, l2); f16_split(brv[p].w, h3, l3);
            __half2* pb = (__half2*)&Bh[row * HSTR + g_c];
            pb[0] = __halves2half2(h0, h1); pb[1] = __halves2half2(h2, h3);
            __half2* pbl = (__half2*)&Bl[row * HSTR + g_c];
            pbl[0] = __halves2half2(l0, l1); pbl[1] = __halves2half2(l2, l3);
        }
    };

    auto compute = [&](int buf) {
        const __half* Ah = hsm + buf * BUFH;
        const __half* Al = Ah + HTILE;
        const __half* Bh = Al + HTILE;
        const __half* Bl = Bh + HTILE;
#pragma unroll
        for (int ks = 0; ks < GBK / 16; ks++) {
            int kc = ks * 16 + 2 * tig;
            uint32_t ah[2][4], al[2][4];
#pragma unroll
            for (int mt = 0; mt < 2; mt++) {
                int rm = wm * 32 + mt * 16;
                ah[mt][0] = *(const uint32_t*)&Ah[(rm + gid) * HSTR + kc];
                ah[mt][1] = *(const uint32_t*)&Ah[(rm + gid + 8) * HSTR + kc];
                ah[mt][2] = *(const uint32_t*)&Ah[(rm + gid) * HSTR + kc + 8];
                ah[mt][3] = *(const uint32_t*)&Ah[(rm + gid + 8) * HSTR + kc + 8];
                al[mt][0] = *(const uint32_t*)&Al[(rm + gid) * HSTR + kc];
                al[mt][1] = *(const uint32_t*)&Al[(rm + gid + 8) * HSTR + kc];
                al[mt][2] = *(const uint32_t*)&Al[(rm + gid) * HSTR + kc + 8];
                al[mt][3] = *(const uint32_t*)&Al[(rm + gid + 8) * HSTR + kc + 8];
            }
            uint32_t bh[4][2], bl[4][2];
#pragma unroll
            for (int nt = 0; nt < 4; nt++) {
                int cn = wn * 32 + nt * 8 + gid;
                bh[nt][0] = *(const uint32_t*)&Bh[cn * HSTR + kc];
                bh[nt][1] = *(const uint32_t*)&Bh[cn * HSTR + kc + 8];
                bl[nt][0] = *(const uint32_t*)&Bl[cn * HSTR + kc];
                bl[nt][1] = *(const uint32_t*)&Bl[cn * HSTR + kc + 8];
            }
#pragma unroll
            for (int mt = 0; mt < 2; mt++)
#pragma unroll
                for (int nt = 0; nt < 4; nt++) {
                    mma_f16(acc[mt][nt], ah[mt][0], ah[mt][1], ah[mt][2], ah[mt][3],
                            bl[nt][0], bl[nt][1]);
                    mma_f16(acc[mt][nt], al[mt][0], al[mt][1], al[mt][2], al[mt][3],
                            bh[nt][0], bh[nt][1]);
                    mma_f16(acc[mt][nt], ah[mt][0], ah[mt][1], ah[mt][2], ah[mt][3],
                            bh[nt][0], bh[nt][1]);
                }
        }
    };

    int T = K / GBK;
    loadG(0);
    storeSplit(0);
    __syncthreads();
    for (int t = 0; t < T; t++) {
        int buf = t & 1;
        bool more = (t + 1 < T);
        if (more) loadG(t + 1);
        compute(buf);
        if (more) storeSplit(buf ^ 1);
        __syncthreads();
    }

#pragma unroll
    for (int mt = 0; mt < 2; mt++) {
        int rbase = m0 + wm * 32 + mt * 16 + gid;
#pragma unroll
        for (int nt = 0; nt < 4; nt++) {
            int c0 = n0 + wn * 32 + nt * 8 + tig * 2;
            float bia0 = bias[c0], bia1 = bias[c0 + 1];
#pragma unroll
            for (int half = 0; half < 2; half++) {
                int m = rbase + half * 8;
                if (m >= M) continue;
                float v0 = acc[mt][nt][half * 2 + 0] + bia0;
                float v1 = acc[mt][nt][half * 2 + 1] + bia1;
                if (doRelu) { v0 = fmaxf(v0, 0.f); v1 = fmaxf(v1, 0.f); }
                C[(size_t)m * N + c0] = v0;
                C[(size_t)m * N + c0 + 1] = v1;
            }
        }
    }
}

// -------- softmax(relu(h3)) warp-per-row + argmax (shuffle-only) ---------------
__global__ __launch_bounds__(256) void k_softmax(const float* __restrict__ H,
                                                 float* __restrict__ S) {
    int w = blockIdx.x * 8 + (threadIdx.x >> 5);
    int lane = threadIdx.x & 31;
    if (w >= NN) return;
    const float4* Hr = (const float4*)(H + (size_t)w * CC);
    float4 v[4];
    float vmax = -1e30f;
    int vidx = 0x7FFFFFFF;
#pragma unroll
    for (int r = 0; r < 4; r++) {
        v[r] = Hr[r * 32 + lane];
        v[r].x = fmaxf(v[r].x, 0.f);
        v[r].y = fmaxf(v[r].y, 0.f);
        v[r].z = fmaxf(v[r].z, 0.f);
        v[r].w = fmaxf(v[r].w, 0.f);
        int c0 = (r * 32 + lane) * 4;
        // strict > keeps FIRST max within this lane's ascending-index stream
        if (v[r].x > vmax) { vmax = v[r].x; vidx = c0 + 0; }
        if (v[r].y > vmax) { vmax = v[r].y; vidx = c0 + 1; }
        if (v[r].z > vmax) { vmax = v[r].z; vidx = c0 + 2; }
        if (v[r].w > vmax) { vmax = v[r].w; vidx = c0 + 3; }
    }
#pragma unroll
    for (int off = 16; off > 0; off >>= 1) {
        float om = __shfl_xor_sync(0xFFFFFFFFu, vmax, off);
        int oi = __shfl_xor_sync(0xFFFFFFFFu, vidx, off);
        if (om > vmax || (om == vmax && oi < vidx)) { vmax = om; vidx = oi; }
    }
    float e[16];
    float sum = 0.0f;
#pragma unroll
    for (int r = 0; r < 4; r++) {
        e[r * 4 + 0] = expf(v[r].x - vmax);
        e[r * 4 + 1] = expf(v[r].y - vmax);
        e[r * 4 + 2] = expf(v[r].z - vmax);
        e[r * 4 + 3] = expf(v[r].w - vmax);
        sum += e[r * 4 + 0] + e[r * 4 + 1] + e[r * 4 + 2] + e[r * 4 + 3];
    }
#pragma unroll
    for (int off = 16; off > 0; off >>= 1) sum += __shfl_xor_sync(0xFFFFFFFFu, sum, off);
    float inv = 1.0f / sum;
    float4* Sr = (float4*)(S + (size_t)w * CC);
#pragma unroll
    for (int r = 0; r < 4; r++)
        Sr[r * 32 + lane] = make_float4(e[r * 4 + 0] * inv, e[r * 4 + 1] * inv,
                                        e[r * 4 + 2] * inv, e[r * 4 + 3] * inv);
    if (lane == 0) g_cluster[w] = vidx;
}

// ---------------- score layer ------------------------------------------------
__global__ void k_hs(const float* __restrict__ x, const float* __restrict__ Ws) {
    int t = blockIdx.x * blockDim.x + threadIdx.x;
    int w = t >> 5, lane = t & 31;
    if (w >= NN) return;
    float a = 0.0f;
#pragma unroll
    for (int r = 0; r < 4; r++) {
        int f = lane + 32 * r;
        a += x[(size_t)w * FF + f] * Ws[f];
    }
#pragma unroll
    for (int off = 16; off > 0; off >>= 1) a += __shfl_down_sync(0xFFFFFFFFu, a, off);
    if (lane == 0) g_hs[w] = a;
}

__global__ void k_intra() {  // intra-degree -> invs, ivh; mark nonempty clusters
    int t = blockIdx.x * blockDim.x + threadIdx.x;
    int i = t >> 5, lane = t & 31;
    if (i >= NN) return;
    int myc = g_cluster[i];
    int beg = g_rowstart[i], end = beg + g_cnt[i];
    int cint = 0;
    for (int j = beg + lane; j < end; j += 32)
        cint += (g_cluster[g_csr[j]] == myc) ? 1 : 0;
#pragma unroll
    for (int off = 16; off > 0; off >>= 1) cint += __shfl_down_sync(0xFFFFFFFFu, cint, off);
    if (lane == 0) {
        float iv = rsqrtf((float)cint + 1.0f);
        g_invs[i] = iv;
        g_ivh[i] = iv * g_hs[i];
        if (cint > 0) atomicOr(&g_nonempty[myc], 1);
    }
}

__global__ void k_score(const float* __restrict__ bs) {
    int t = blockIdx.x * blockDim.x + threadIdx.x;
    int i = t >> 5, lane = t & 31;
    if (i >= NN) return;
    int myc = g_cluster[i];
    int beg = g_rowstart[i], end = beg + g_cnt[i];
    float acc = 0.0f;
    for (int j = beg + lane; j < end; j += 32) {
        int s = g_csr[j];
        if (g_cluster[s] == myc) acc += g_ivh[s];
    }
#pragma unroll
    for (int off = 16; off > 0; off >>= 1) acc += __shfl_down_sync(0xFFFFFFFFu, acc, off);
    if (lane == 0) {
        float invi = g_invs[i];
        float agg = invi * (acc + g_ivh[i]);
        g_score[i] = tanhf(agg + bs[0]);
    }
}

// fused per-cluster max score + first-argmax via one 64-bit atomicMax
__global__ void k_seg() {
    int i = blockIdx.x * blockDim.x + threadIdx.x;
    if (i >= NN) return;
    unsigned long long key =
        ((unsigned long long)fkey(g_score[i]) << 32) |
        (unsigned)(0x7FFFFFFF - i);
    atomicMax(&g_ckey[g_cluster[i]], key);
}

// ---------------- outputs ----------------------------------------------------
__global__ void k_newx(const float* __restrict__ x, float* __restrict__ out) {
    int c = blockIdx.x, f = threadIdx.x;
    float v = 0.0f;
    if (g_nonempty[c]) {
        unsigned long long key = g_ckey[c];
        float alpha = fdec((unsigned)(key >> 32));
        int id = 0x7FFFFFFF - (int)(key & 0xFFFFFFFFull);
        v = x[(size_t)id * FF + f] * alpha;
    }
    out[(size_t)c * FF + f] = v;
}

__global__ void k_zero(float* __restrict__ p, int n) {
    int i = blockIdx.x * blockDim.x + threadIdx.x;
    if (i < n) p[i] = 0.0f;
}

__global__ void k_adj(const int* __restrict__ src, const int* __restrict__ dst,
                      float* __restrict__ adj) {
    int e = blockIdx.x * blockDim.x + threadIdx.x;
    if (e >= EE) return;
    int ci = g_cluster[src[e]], cj = g_cluster[dst[e]];
    if (ci != cj && g_nonempty[ci] && g_nonempty[cj]) adj[ci * CC + cj] = 1.0f;
}

// ---------------- host -------------------------------------------------------
extern "C" void kernel_launch(void* const* d_in, const int* in_sizes, int n_in,
                              void* d_out, int out_size) {
    const float* x  = (const float*)d_in[0];
    const int*   ei = (const int*)d_in[1];
    const int*   src = ei;
    const int*   dst = ei + EE;
    const float* W1 = (const float*)d_in[3];
    const float* b1 = (const float*)d_in[4];
    const float* W2 = (const float*)d_in[5];
    const float* b2 = (const float*)d_in[6];
    const float* W3 = (const float*)d_in[7];
    const float* b3 = (const float*)d_in[8];
    const float* Ws = (const float*)d_in[9];
    const float* bs = (const float*)d_in[10];

    float* out      = (float*)d_out;
    float* out_newx = out;
    float* out_adj  = out + (size_t)CC * FF;
    float* out_S    = out + (size_t)CC * FF + (size_t)CC * CC + CC;

    float *pP, *ph, *ph3, *pWt;
    cudaGetSymbolAddress((void**)&pP,  g_P);
    cudaGetSymbolAddress((void**)&ph,  g_h);
    cudaGetSymbolAddress((void**)&ph3, g_h3);
    cudaGetSymbolAddress((void**)&pWt, g_Wt);

    cudaFuncSetAttribute(k_gemm_fp16, cudaFuncAttributeMaxDynamicSharedMemorySize,
                         GEMM_SMEM_BYTES);

    const int TB = 256;
    int gN = (NN + TB - 1) / TB;
    int gE = (EE + TB - 1) / TB;
    int gW = (NN * 32 + TB - 1) / TB;
    int gP = (NN + 7) / 8;
    int nbScan = (NN + 1023) / 1024;
    int gM = (NN + GBM - 1) / GBM;

    // graph build (CSR) + degree normalization
    k_init<<<gN, TB>>>();
    k_count<<<gE, TB>>>(dst);
    k_scan1<<<nbScan, 1024>>>();
    k_scan2<<<1, 32>>>(nbScan);
    k_scan3<<<gN, TB>>>();
    k_scatter<<<gE, TB>>>(src, dst);

    // 3-layer GCN: propagate (input space) -> fp16x3 tensor-core linear
    dim3 tb(32, 8);
    k_prop<FF><<<gP, TB>>>(x, pP);
    k_transW<<<dim3(HH / 32, FF / 32), tb>>>(W1, pWt, FF, HH);
    k_gemm_fp16<<<dim3(HH / GBN, gM), 512, GEMM_SMEM_BYTES>>>(pP, pWt, b1, ph, NN, HH, FF, 1);
    k_prop<HH><<<gP, TB>>>(ph, pP);
    k_transW<<<dim3(HH / 32, HH / 32), tb>>>(W2, pWt, HH, HH);
    k_gemm_fp16<<<dim3(HH / GBN, gM), 512, GEMM_SMEM_BYTES>>>(pP, pWt, b2, ph, NN, HH, HH, 1);
    k_prop<HH><<<gP, TB>>>(ph, pP);
    k_transW<<<dim3(CC / 32, HH / 32), tb>>>(W3, pWt, HH, CC);
    k_gemm_fp16<<<dim3(CC / GBN, gM), 512, GEMM_SMEM_BYTES>>>(pP, pWt, b3, ph3, NN, CC, HH, 0);

    // softmax(relu) -> S output + hard clusters (warp-per-row)
    k_softmax<<<(NN + 7) / 8, 256>>>(ph3, out_S);

    // score layer on intra-cluster subgraph
    k_hs<<<gW, TB>>>(x, Ws);
    k_intra<<<gW, TB>>>();
    k_score<<<gW, TB>>>(bs);
    k_seg<<<gN, TB>>>();

    // pooled outputs
    k_newx<<<CC, FF>>>(x, out_newx);
    int zn = CC * CC + CC;
    k_zero<<<(zn + TB - 1) / TB, TB>>>(out_adj, zn);
    k_adj<<<gE, TB>>>(src, dst, out_adj);
}